// round 2
// baseline (speedup 1.0000x reference)
#include <cuda_runtime.h>
#include <math.h>

#define LSEQ 512
#define NB   64
#define KIN  38
#define EDIM 1024
#define HDIM 1024
#define NL   3
#define NC   38
#define H3   (3*HDIM)

#define GRU_BLOCKS 128
#define GRU_THREADS 128

// ---------------- scratch (device globals; no allocations allowed) ----------
__device__ float g_bufA[(size_t)LSEQ * NB * EDIM];          // 128 MB
__device__ float g_bufB[(size_t)LSEQ * NB * EDIM];          // 128 MB
__device__ float g_xg[(size_t)LSEQ * NB * H3];              // 384 MB
__device__ float g_h[2 * NB * HDIM];                        // ping-pong hidden

// software grid barrier state
__device__ volatile unsigned g_gen = 0;
__device__ unsigned g_arrive = 0;

__device__ __forceinline__ void grid_barrier(unsigned nblk) {
    __syncthreads();
    if (threadIdx.x == 0) {
        unsigned old_gen = g_gen;
        __threadfence();
        unsigned a = atomicAdd(&g_arrive, 1u);
        if (a == nblk - 1u) {
            g_arrive = 0;
            __threadfence();
            g_gen = old_gen + 1u;
        } else {
            while (g_gen == old_gen) { }
            __threadfence();
        }
    }
    __syncthreads();
}

// ---------------- embedding: x = inputs @ emb_W^T + emb_b -------------------
__global__ void embed_kernel(const float* __restrict__ in,
                             const float* __restrict__ W,
                             const float* __restrict__ b,
                             float* __restrict__ out) {
    int ln = blockIdx.x;                       // 0..L*N-1
    int e  = blockIdx.y * 256 + threadIdx.x;   // 0..E-1
    __shared__ float xs[KIN];
    if (threadIdx.x < KIN) xs[threadIdx.x] = in[(size_t)ln * KIN + threadIdx.x];
    __syncthreads();
    float acc = b[e];
    const float* w = W + (size_t)e * KIN;
#pragma unroll
    for (int k = 0; k < KIN; k++) acc = fmaf(xs[k], w[k], acc);
    out[(size_t)ln * EDIM + e] = acc;
}

// ---------------- fp32 SGEMM (NT): C[m,n] = sum_k A[m,k]*B[n,k] + bias[n] ---
__global__ void sgemm_nt_bias(const float* __restrict__ A,
                              const float* __restrict__ B,
                              const float* __restrict__ bias,
                              float* __restrict__ C,
                              int M, int N, int Kd) {
    __shared__ float As[8][128];
    __shared__ float Bs[8][128];
    const int tid = threadIdx.x;
    const int bm = blockIdx.y * 128;
    const int bn = blockIdx.x * 128;

    const int lr = tid >> 1;          // 0..127
    const int lk = (tid & 1) * 4;     // 0 or 4

    const float* Aptr = A + (size_t)(bm + lr) * Kd;
    const float* Bptr = B + (size_t)(bn + lr) * Kd;

    const int tm0 = (tid >> 4) * 8;   // 0..120
    const int tn0 = (tid & 15) * 8;   // 0..120

    float acc[8][8];
#pragma unroll
    for (int i = 0; i < 8; i++)
#pragma unroll
        for (int j = 0; j < 8; j++) acc[i][j] = 0.f;

    for (int k0 = 0; k0 < Kd; k0 += 8) {
        float4 a4 = *(const float4*)(Aptr + k0 + lk);
        float4 b4 = *(const float4*)(Bptr + k0 + lk);
        As[lk + 0][lr] = a4.x; As[lk + 1][lr] = a4.y;
        As[lk + 2][lr] = a4.z; As[lk + 3][lr] = a4.w;
        Bs[lk + 0][lr] = b4.x; Bs[lk + 1][lr] = b4.y;
        Bs[lk + 2][lr] = b4.z; Bs[lk + 3][lr] = b4.w;
        __syncthreads();
#pragma unroll
        for (int kk = 0; kk < 8; kk++) {
            float4 ra0 = *(const float4*)&As[kk][tm0];
            float4 ra1 = *(const float4*)&As[kk][tm0 + 4];
            float4 rb0 = *(const float4*)&Bs[kk][tn0];
            float4 rb1 = *(const float4*)&Bs[kk][tn0 + 4];
            float ra[8] = {ra0.x, ra0.y, ra0.z, ra0.w, ra1.x, ra1.y, ra1.z, ra1.w};
            float rb[8] = {rb0.x, rb0.y, rb0.z, rb0.w, rb1.x, rb1.y, rb1.z, rb1.w};
#pragma unroll
            for (int i = 0; i < 8; i++)
#pragma unroll
                for (int j = 0; j < 8; j++)
                    acc[i][j] = fmaf(ra[i], rb[j], acc[i][j]);
        }
        __syncthreads();
    }

#pragma unroll
    for (int i = 0; i < 8; i++) {
        float* crow = C + (size_t)(bm + tm0 + i) * N + bn + tn0;
#pragma unroll
        for (int j = 0; j < 8; j++)
            crow[j] = acc[i][j] + bias[bn + tn0 + j];
    }
}

// ---------------- persistent GRU layer kernel --------------------------------
// 128 blocks x 128 threads, one block per SM (single wave -> spin barrier safe).
// Block owns 8 hidden columns. Weights (24 rows x 1024) cached in smem for all
// 512 timesteps. Thread: 1 col x 4 batches x 3 gates = 12 accumulators.
__device__ __forceinline__ float sigmoidf_(float x) {
    return 1.f / (1.f + expf(-x));
}

__global__ void __launch_bounds__(GRU_THREADS, 1)
gru_layer_kernel(const float* __restrict__ xg,   // (L, NB, 3H)
                 const float* __restrict__ whh,  // (3H, H)
                 const float* __restrict__ bhh,  // (3H)
                 float* __restrict__ hbuf,       // 2 * NB * HDIM
                 float* __restrict__ y) {        // (L, NB, H)
    extern __shared__ float sm[];
    float* ws = sm;                    // [1024][25]  (k-major, 24 rows + pad)
    float* hs = sm + 1024 * 25;        // [64][68]    (batch-major h tile + pad)

    const int tid = threadIdx.x;
    const int j0 = blockIdx.x * 8;
    const int j  = tid & 7;
    const int bq = tid >> 3;           // 0..15
    const int b0 = bq * 4;

    // ---- load weight tile into smem once (transposed: ws[k][gate*8+col]) ----
    for (int idx = tid; idx < 24 * 256; idx += GRU_THREADS) {
        int r  = idx >> 8;             // 0..23
        int kq = (idx & 255) * 4;      // k offset
        int g = r >> 3, jj = r & 7;
        float4 v = *(const float4*)(whh + (size_t)(g * HDIM + j0 + jj) * HDIM + kq);
        ws[(kq + 0) * 25 + r] = v.x;
        ws[(kq + 1) * 25 + r] = v.y;
        ws[(kq + 2) * 25 + r] = v.z;
        ws[(kq + 3) * 25 + r] = v.w;
    }

    // ---- zero h0 (buffer 0) cooperatively ----
    {
        const int total = NB * HDIM;                       // 65536
        const int per = total / (GRU_BLOCKS * GRU_THREADS); // 4
        int base = (blockIdx.x * GRU_THREADS + tid) * per;
#pragma unroll
        for (int q = 0; q < 4; q++) hbuf[base + q] = 0.f;
        (void)per;
    }

    const int ja = j0 + j;
    const float br = bhh[ja];
    const float bz = bhh[HDIM + ja];
    const float bn = bhh[2 * HDIM + ja];

    grid_barrier(GRU_BLOCKS);

    for (int t = 0; t < LSEQ; t++) {
        const float* h_in  = hbuf + (size_t)(t & 1) * (NB * HDIM);
        float*       h_out = hbuf + (size_t)((t + 1) & 1) * (NB * HDIM);
        const float* xg_t  = xg + (size_t)t * NB * H3;
        float*       y_t   = y  + (size_t)t * NB * HDIM;

        float acc[12];
#pragma unroll
        for (int i = 0; i < 12; i++) acc[i] = 0.f;

        for (int k0 = 0; k0 < HDIM; k0 += 64) {
            __syncthreads();
            // load h tile (batch-major, coalesced): hs[b][kk]
            {
                int b  = tid >> 1;             // 0..63
                int kq = (tid & 1) * 32;       // 0 or 32
                const float* hp = h_in + (size_t)b * HDIM + k0 + kq;
                float* hd = hs + b * 68 + kq;
#pragma unroll
                for (int q = 0; q < 8; q++) {
                    float4 v = *(const float4*)(hp + q * 4);
                    *(float4*)(hd + q * 4) = v;
                }
            }
            __syncthreads();
#pragma unroll 8
            for (int kk = 0; kk < 64; kk++) {
                const float* wrow = ws + (size_t)(k0 + kk) * 25;
                float wr = wrow[j];
                float wz = wrow[8 + j];
                float wn = wrow[16 + j];
                float h0v = hs[(b0 + 0) * 68 + kk];
                float h1v = hs[(b0 + 1) * 68 + kk];
                float h2v = hs[(b0 + 2) * 68 + kk];
                float h3v = hs[(b0 + 3) * 68 + kk];
                acc[0]  = fmaf(h0v, wr, acc[0]);
                acc[1]  = fmaf(h0v, wz, acc[1]);
                acc[2]  = fmaf(h0v, wn, acc[2]);
                acc[3]  = fmaf(h1v, wr, acc[3]);
                acc[4]  = fmaf(h1v, wz, acc[4]);
                acc[5]  = fmaf(h1v, wn, acc[5]);
                acc[6]  = fmaf(h2v, wr, acc[6]);
                acc[7]  = fmaf(h2v, wz, acc[7]);
                acc[8]  = fmaf(h2v, wn, acc[8]);
                acc[9]  = fmaf(h3v, wr, acc[9]);
                acc[10] = fmaf(h3v, wz, acc[10]);
                acc[11] = fmaf(h3v, wn, acc[11]);
            }
        }

        // ---- gates + state update ----
#pragma unroll
        for (int i = 0; i < 4; i++) {
            int b = b0 + i;
            float hr = acc[i * 3 + 0] + br;
            float hz = acc[i * 3 + 1] + bz;
            float hn = acc[i * 3 + 2] + bn;
            const float* xrow = xg_t + (size_t)b * H3 + ja;
            float r = sigmoidf_(xrow[0] + hr);
            float z = sigmoidf_(xrow[HDIM] + hz);
            float n = tanhf(xrow[2 * HDIM] + r * hn);
            float hprev = h_in[(size_t)b * HDIM + ja];
            float hnew = (1.f - z) * n + z * hprev;
            h_out[(size_t)b * HDIM + ja] = hnew;
            y_t[(size_t)b * HDIM + ja] = hnew;
        }

        grid_barrier(GRU_BLOCKS);
    }
}

// ---------------- output projection: logits = x @ out_W^T + out_b -----------
__global__ void outproj_kernel(const float* __restrict__ x,
                               const float* __restrict__ W,
                               const float* __restrict__ b,
                               float* __restrict__ out) {
    int ln = blockIdx.x;
    __shared__ float xs[HDIM];
    const float* xr = x + (size_t)ln * HDIM;
    for (int k = threadIdx.x; k < HDIM; k += 256) xs[k] = xr[k];
    __syncthreads();
    int warp = threadIdx.x >> 5, lane = threadIdx.x & 31;
    for (int c = warp; c < NC; c += 8) {
        const float* w = W + (size_t)c * HDIM;
        float acc = 0.f;
        for (int k = lane; k < HDIM; k += 32) acc = fmaf(xs[k], w[k], acc);
#pragma unroll
        for (int o = 16; o; o >>= 1) acc += __shfl_xor_sync(0xffffffffu, acc, o);
        if (lane == 0) out[(size_t)ln * NC + c] = acc + b[c];
    }
}

// ---------------- orchestration ---------------------------------------------
extern "C" void kernel_launch(void* const* d_in, const int* in_sizes, int n_in,
                              void* d_out, int out_size) {
    const float* inputs = (const float*)d_in[0];
    const float* emb_W  = (const float*)d_in[1];
    const float* emb_b  = (const float*)d_in[2];
    const float* w_ih   = (const float*)d_in[3];
    const float* w_hh   = (const float*)d_in[4];
    const float* b_ih   = (const float*)d_in[5];
    const float* b_hh   = (const float*)d_in[6];
    const float* out_W  = (const float*)d_in[7];
    const float* out_b  = (const float*)d_in[8];
    float* out = (float*)d_out;

    float *bufA, *bufB, *xg, *hbuf;
    cudaGetSymbolAddress((void**)&bufA, g_bufA);
    cudaGetSymbolAddress((void**)&bufB, g_bufB);
    cudaGetSymbolAddress((void**)&xg,   g_xg);
    cudaGetSymbolAddress((void**)&hbuf, g_h);

    const int GRU_SMEM = (1024 * 25 + 64 * 68) * 4;   // 119808 bytes
    cudaFuncSetAttribute(gru_layer_kernel,
                         cudaFuncAttributeMaxDynamicSharedMemorySize, GRU_SMEM);

    const int M = LSEQ * NB;

    // 1) embedding
    {
        dim3 grid(M, EDIM / 256);
        embed_kernel<<<grid, 256>>>(inputs, emb_W, emb_b, bufA);
    }

    float* x = bufA;
    float* y = bufB;

    for (int l = 0; l < NL; l++) {
        // 2a) input projection for whole sequence: xg = x @ w_ih[l]^T + b_ih[l]
        {
            dim3 grid(H3 / 128, M / 128);
            sgemm_nt_bias<<<grid, 256>>>(x,
                                         w_ih + (size_t)l * H3 * EDIM,
                                         b_ih + (size_t)l * H3,
                                         xg, M, H3, EDIM);
        }
        // 2b) persistent recurrence over all 512 steps (single launch)
        gru_layer_kernel<<<GRU_BLOCKS, GRU_THREADS, GRU_SMEM>>>(
            xg,
            w_hh + (size_t)l * H3 * HDIM,
            b_hh + (size_t)l * H3,
            hbuf,
            y);
        // swap
        float* tmp = x; x = y; y = tmp;
    }

    // 3) output projection (final layer output is in x after the swap)
    outproj_kernel<<<M, 256>>>(x, out_W, out_b, out);

    (void)in_sizes; (void)n_in; (void)out_size;
}

// round 3
// speedup vs baseline: 2.0303x; 2.0303x over previous
#include <cuda_runtime.h>
#include <cuda_bf16.h>
#include <math.h>
#include <stdint.h>

#define LSEQ 512
#define NB   64
#define KIN  38
#define EDIM 1024
#define HDIM 1024
#define NL   3
#define NC   38
#define H3   (3*HDIM)

#define GRU_BLOCKS 128

// ---------------- scratch (device globals; no allocations allowed) ----------
__device__ __align__(16) float         g_xg[(size_t)LSEQ * NB * H3];      // 384 MB
__device__ __align__(16) __nv_bfloat16 g_y_hi[(size_t)LSEQ * NB * EDIM];  // 64 MB
__device__ __align__(16) __nv_bfloat16 g_y_lo[(size_t)LSEQ * NB * EDIM];  // 64 MB
__device__ __align__(16) __nv_bfloat16 g_h_hi[2 * NB * HDIM];
__device__ __align__(16) __nv_bfloat16 g_h_lo[2 * NB * HDIM];
__device__ __align__(16) __nv_bfloat16 g_wih_hi[(size_t)NL * H3 * EDIM];  // 18.9 MB
__device__ __align__(16) __nv_bfloat16 g_wih_lo[(size_t)NL * H3 * EDIM];
__device__ __align__(16) __nv_bfloat16 g_whh_hi[(size_t)NL * H3 * HDIM];
__device__ __align__(16) __nv_bfloat16 g_whh_lo[(size_t)NL * H3 * HDIM];

// software grid barrier state
__device__ volatile unsigned g_gen = 0;
__device__ unsigned g_arrive = 0;

__device__ __forceinline__ void grid_barrier(unsigned nblk) {
    __syncthreads();
    if (threadIdx.x == 0) {
        unsigned old_gen = g_gen;
        __threadfence();
        unsigned a = atomicAdd(&g_arrive, 1u);
        if (a == nblk - 1u) {
            g_arrive = 0;
            __threadfence();
            g_gen = old_gen + 1u;
        } else {
            while (g_gen == old_gen) { }
            __threadfence();
        }
    }
    __syncthreads();
}

// ---------------- mma helpers ------------------------------------------------
__device__ __forceinline__ uint32_t smem_u32(const void* p) {
    return (uint32_t)__cvta_generic_to_shared(p);
}
__device__ __forceinline__ void ldsm_x4(uint32_t* r, uint32_t addr) {
    asm volatile("ldmatrix.sync.aligned.m8n8.x4.shared.b16 {%0,%1,%2,%3},[%4];"
                 : "=r"(r[0]), "=r"(r[1]), "=r"(r[2]), "=r"(r[3]) : "r"(addr));
}
__device__ __forceinline__ void mma16816(float* c, const uint32_t* a,
                                         uint32_t b0, uint32_t b1) {
    asm volatile(
        "mma.sync.aligned.m16n8k16.row.col.f32.bf16.bf16.f32 "
        "{%0,%1,%2,%3},{%4,%5,%6,%7},{%8,%9},{%0,%1,%2,%3};"
        : "+f"(c[0]), "+f"(c[1]), "+f"(c[2]), "+f"(c[3])
        : "r"(a[0]), "r"(a[1]), "r"(a[2]), "r"(a[3]), "r"(b0), "r"(b1));
}
__device__ __forceinline__ void split2(float x, __nv_bfloat16& hi, __nv_bfloat16& lo) {
    hi = __float2bfloat16(x);
    lo = __float2bfloat16(x - __bfloat162float(hi));
}

// ---------------- weight split kernel ----------------------------------------
__global__ void split_kernel(const float* __restrict__ src,
                             __nv_bfloat16* __restrict__ hi,
                             __nv_bfloat16* __restrict__ lo, int n) {
    for (int i = blockIdx.x * 256 + threadIdx.x; i < n; i += gridDim.x * 256) {
        float x = src[i];
        __nv_bfloat16 h = __float2bfloat16(x);
        hi[i] = h;
        lo[i] = __float2bfloat16(x - __bfloat162float(h));
    }
}

// ---------------- embedding: y = split(inputs @ emb_W^T + emb_b) -------------
__global__ void embed_kernel(const float* __restrict__ in,
                             const float* __restrict__ W,
                             const float* __restrict__ b,
                             __nv_bfloat16* __restrict__ yhi,
                             __nv_bfloat16* __restrict__ ylo) {
    int ln = blockIdx.x;
    int e  = blockIdx.y * 256 + threadIdx.x;
    __shared__ float xs[KIN];
    if (threadIdx.x < KIN) xs[threadIdx.x] = in[(size_t)ln * KIN + threadIdx.x];
    __syncthreads();
    float acc = b[e];
    const float* w = W + (size_t)e * KIN;
#pragma unroll
    for (int k = 0; k < KIN; k++) acc = fmaf(xs[k], w[k], acc);
    __nv_bfloat16 hh, hl;
    split2(acc, hh, hl);
    yhi[(size_t)ln * EDIM + e] = hh;
    ylo[(size_t)ln * EDIM + e] = hl;
}

// ---------------- bf16-split MMA GEMM: xg = x @ w_ih^T + b_ih ----------------
// C[m,n] = sum_k A[m,k] * B[n,k], A = x (hi/lo), B = w_ih rows (hi/lo).
// BM=128, BN=64, BK=32, 256 threads (8 warps: 4m x 2n, warp tile m32 x n32).
__global__ void __launch_bounds__(256)
gemm_xg_mma(const __nv_bfloat16* __restrict__ Ahi,
            const __nv_bfloat16* __restrict__ Alo,
            const __nv_bfloat16* __restrict__ Bhi,
            const __nv_bfloat16* __restrict__ Blo,
            const float* __restrict__ bias,
            float* __restrict__ C) {
    __shared__ __nv_bfloat16 sA[2][128][40];
    __shared__ __nv_bfloat16 sB[2][64][40];
    const int tid = threadIdx.x, lane = tid & 31, warp = tid >> 5;
    const int wm = warp >> 1, wn = warp & 1;
    const int bm = blockIdx.y * 128, bn = blockIdx.x * 64;

    float c[2][4][4];
#pragma unroll
    for (int m = 0; m < 2; m++)
#pragma unroll
        for (int n = 0; n < 4; n++)
#pragma unroll
            for (int q = 0; q < 4; q++) c[m][n][q] = 0.f;

    for (int k0 = 0; k0 < EDIM; k0 += 32) {
        __syncthreads();
        for (int i = tid; i < 512; i += 256) {
            int r = i >> 2, cv = i & 3;
            *(uint4*)&sA[0][r][cv * 8] = *(const uint4*)(Ahi + (size_t)(bm + r) * EDIM + k0 + cv * 8);
            *(uint4*)&sA[1][r][cv * 8] = *(const uint4*)(Alo + (size_t)(bm + r) * EDIM + k0 + cv * 8);
        }
        if (tid < 256) {
            int r = tid >> 2, cv = tid & 3;
            *(uint4*)&sB[0][r][cv * 8] = *(const uint4*)(Bhi + (size_t)(bn + r) * EDIM + k0 + cv * 8);
            *(uint4*)&sB[1][r][cv * 8] = *(const uint4*)(Blo + (size_t)(bn + r) * EDIM + k0 + cv * 8);
        }
        __syncthreads();

        uint32_t a[2][2][2][4];   // [split][m16][k16][4]
#pragma unroll
        for (int s = 0; s < 2; s++)
#pragma unroll
            for (int m = 0; m < 2; m++) {
                int arow = wm * 32 + m * 16 + (lane & 15);
                int acol = (lane >> 4) * 8;
                uint32_t ad = smem_u32(&sA[s][arow][acol]);
                ldsm_x4(a[s][m][0], ad);
                ldsm_x4(a[s][m][1], ad + 32);
            }
        uint32_t bf[2][4][4];     // [split][n8][4] (covers k32)
#pragma unroll
        for (int s = 0; s < 2; s++)
#pragma unroll
            for (int n = 0; n < 4; n++) {
                int brow = wn * 32 + n * 8 + (lane & 7);
                int bcol = (lane >> 3) * 8;
                ldsm_x4(bf[s][n], smem_u32(&sB[s][brow][bcol]));
            }
#pragma unroll
        for (int m = 0; m < 2; m++)
#pragma unroll
            for (int n = 0; n < 4; n++)
#pragma unroll
                for (int k = 0; k < 2; k++) {
                    mma16816(c[m][n], a[0][m][k], bf[0][n][k * 2], bf[0][n][k * 2 + 1]);
                    mma16816(c[m][n], a[0][m][k], bf[1][n][k * 2], bf[1][n][k * 2 + 1]);
                    mma16816(c[m][n], a[1][m][k], bf[0][n][k * 2], bf[0][n][k * 2 + 1]);
                }
    }

#pragma unroll
    for (int m = 0; m < 2; m++) {
        int row0 = bm + wm * 32 + m * 16 + (lane >> 2);
#pragma unroll
        for (int n = 0; n < 4; n++) {
            int col = bn + wn * 32 + n * 8 + (lane & 3) * 2;
            float2 bb = *(const float2*)(bias + col);
            float2 v0 = make_float2(c[m][n][0] + bb.x, c[m][n][1] + bb.y);
            float2 v1 = make_float2(c[m][n][2] + bb.x, c[m][n][3] + bb.y);
            *(float2*)(C + (size_t)row0 * H3 + col) = v0;
            *(float2*)(C + (size_t)(row0 + 8) * H3 + col) = v1;
        }
    }
}

// ---------------- persistent GRU layer (tensor-core recurrence) --------------
// 128 blocks x 128 threads (4 warps). Block owns 8 hidden cols x 3 gates = 24
// W rows, cached in smem (hi/lo) for all 512 steps. Per step: hg^T = h @ W^T
// via mma (m=64 batch, n=24, k=1024 in 4 chunks of 256), then gates.
#define WS_LD 1032
#define HS_LD 264
#define GRU_SMEM ((2*24*WS_LD + 2*64*HS_LD) * 2)

__device__ __forceinline__ float sigmoidf_(float x) {
    return 1.f / (1.f + expf(-x));
}

__global__ void __launch_bounds__(128, 1)
gru_layer_mma(const float* __restrict__ xg,
              const __nv_bfloat16* __restrict__ whh_hi,
              const __nv_bfloat16* __restrict__ whh_lo,
              const float* __restrict__ bhh,
              __nv_bfloat16* __restrict__ hhi,
              __nv_bfloat16* __restrict__ hlo,
              __nv_bfloat16* __restrict__ yhi,
              __nv_bfloat16* __restrict__ ylo) {
    extern __shared__ __nv_bfloat16 sm[];
    __nv_bfloat16* ws_hi = sm;                     // [24][WS_LD]
    __nv_bfloat16* ws_lo = ws_hi + 24 * WS_LD;
    __nv_bfloat16* hs_hi = ws_lo + 24 * WS_LD;     // [64][HS_LD] (256-col chunk)
    __nv_bfloat16* hs_lo = hs_hi + 64 * HS_LD;

    const int tid  = threadIdx.x;
    const int lane = tid & 31, warp = tid >> 5;
    const int j0 = blockIdx.x * 8;

    // load W tile (rows r = g*8+jj -> global row g*HDIM + j0 + jj)
    for (int i = tid; i < 24 * 128; i += 128) {
        int r = i >> 7, v = i & 127;
        int grow = (r >> 3) * HDIM + j0 + (r & 7);
        *(uint4*)&ws_hi[r * WS_LD + v * 8] = *(const uint4*)(whh_hi + (size_t)grow * HDIM + v * 8);
        *(uint4*)&ws_lo[r * WS_LD + v * 8] = *(const uint4*)(whh_lo + (size_t)grow * HDIM + v * 8);
    }
    // zero h slot 0
    {
        int base = (blockIdx.x * 128 + tid) * 4;
        uint2 z = make_uint2(0u, 0u);
        *(uint2*)&hhi[base] = z;
        *(uint2*)&hlo[base] = z;
    }
    grid_barrier(GRU_BLOCKS);

    for (int t = 0; t < LSEQ; t++) {
        const __nv_bfloat16* hin_hi = hhi + (t & 1) * (NB * HDIM);
        const __nv_bfloat16* hin_lo = hlo + (t & 1) * (NB * HDIM);
        __nv_bfloat16* hout_hi = hhi + ((t + 1) & 1) * (NB * HDIM);
        __nv_bfloat16* hout_lo = hlo + ((t + 1) & 1) * (NB * HDIM);
        const float* xg_t = xg + (size_t)t * NB * H3;

        float c[3][4];
#pragma unroll
        for (int i = 0; i < 3; i++)
#pragma unroll
            for (int q = 0; q < 4; q++) c[i][q] = 0.f;

        for (int kc = 0; kc < 4; kc++) {
            const int k0 = kc * 256;
            __syncthreads();
            for (int i = tid; i < 64 * 32; i += 128) {
                int rw = i >> 5, cv = i & 31;
                *(uint4*)&hs_hi[rw * HS_LD + cv * 8] = *(const uint4*)(hin_hi + rw * HDIM + k0 + cv * 8);
                *(uint4*)&hs_lo[rw * HS_LD + cv * 8] = *(const uint4*)(hin_lo + rw * HDIM + k0 + cv * 8);
            }
            __syncthreads();
#pragma unroll 2
            for (int k32 = 0; k32 < 8; k32++) {
                uint32_t a_hi[2][4], a_lo[2][4];
                {
                    int arow = warp * 16 + (lane & 15);
                    int acol = k32 * 32 + (lane >> 4) * 8;
                    uint32_t ah = smem_u32(&hs_hi[arow * HS_LD + acol]);
                    uint32_t al = smem_u32(&hs_lo[arow * HS_LD + acol]);
                    ldsm_x4(a_hi[0], ah);  ldsm_x4(a_hi[1], ah + 32);
                    ldsm_x4(a_lo[0], al);  ldsm_x4(a_lo[1], al + 32);
                }
                uint32_t b_hi[3][4], b_lo[3][4];
                int bkcol = k0 + k32 * 32 + (lane >> 3) * 8;
#pragma unroll
                for (int n8 = 0; n8 < 3; n8++) {
                    int brow = n8 * 8 + (lane & 7);
                    ldsm_x4(b_hi[n8], smem_u32(&ws_hi[brow * WS_LD + bkcol]));
                    ldsm_x4(b_lo[n8], smem_u32(&ws_lo[brow * WS_LD + bkcol]));
                }
#pragma unroll
                for (int n8 = 0; n8 < 3; n8++)
#pragma unroll
                    for (int k = 0; k < 2; k++) {
                        mma16816(c[n8], a_hi[k], b_hi[n8][k * 2], b_hi[n8][k * 2 + 1]);
                        mma16816(c[n8], a_hi[k], b_lo[n8][k * 2], b_lo[n8][k * 2 + 1]);
                        mma16816(c[n8], a_lo[k], b_hi[n8][k * 2], b_hi[n8][k * 2 + 1]);
                    }
            }
        }

        // gates + state update: lane holds (2 rows x 2 cols) x 3 gates
#pragma unroll
        for (int q = 0; q < 4; q++) {
            int b  = warp * 16 + (lane >> 2) + ((q >> 1) * 8);
            int jj = (lane & 3) * 2 + (q & 1);
            int ja = j0 + jj;
            float hr = c[0][q] + bhh[ja];
            float hz = c[1][q] + bhh[HDIM + ja];
            float hn = c[2][q] + bhh[2 * HDIM + ja];
            const float* xr = xg_t + (size_t)b * H3 + ja;
            float r = sigmoidf_(xr[0] + hr);
            float z = sigmoidf_(xr[HDIM] + hz);
            float n = tanhf(xr[2 * HDIM] + r * hn);
            float hp = __bfloat162float(hin_hi[b * HDIM + ja]) +
                       __bfloat162float(hin_lo[b * HDIM + ja]);
            float hnew = (1.f - z) * n + z * hp;
            __nv_bfloat16 hh, hl;
            split2(hnew, hh, hl);
            hout_hi[b * HDIM + ja] = hh;
            hout_lo[b * HDIM + ja] = hl;
            yhi[(size_t)t * NB * HDIM + b * HDIM + ja] = hh;
            ylo[(size_t)t * NB * HDIM + b * HDIM + ja] = hl;
        }
        grid_barrier(GRU_BLOCKS);
    }
}

// ---------------- output projection ------------------------------------------
__global__ void outproj_kernel(const __nv_bfloat16* __restrict__ xhi,
                               const __nv_bfloat16* __restrict__ xlo,
                               const float* __restrict__ W,
                               const float* __restrict__ b,
                               float* __restrict__ out) {
    int ln = blockIdx.x;
    __shared__ float xs[HDIM];
    const __nv_bfloat16* xh = xhi + (size_t)ln * HDIM;
    const __nv_bfloat16* xl = xlo + (size_t)ln * HDIM;
    for (int k = threadIdx.x; k < HDIM; k += 256)
        xs[k] = __bfloat162float(xh[k]) + __bfloat162float(xl[k]);
    __syncthreads();
    int warp = threadIdx.x >> 5, lane = threadIdx.x & 31;
    for (int c = warp; c < NC; c += 8) {
        const float* w = W + (size_t)c * HDIM;
        float acc = 0.f;
        for (int k = lane; k < HDIM; k += 32) acc = fmaf(xs[k], w[k], acc);
#pragma unroll
        for (int o = 16; o; o >>= 1) acc += __shfl_xor_sync(0xffffffffu, acc, o);
        if (lane == 0) out[(size_t)ln * NC + c] = acc + b[c];
    }
}

// ---------------- orchestration ---------------------------------------------
extern "C" void kernel_launch(void* const* d_in, const int* in_sizes, int n_in,
                              void* d_out, int out_size) {
    const float* inputs = (const float*)d_in[0];
    const float* emb_W  = (const float*)d_in[1];
    const float* emb_b  = (const float*)d_in[2];
    const float* w_ih   = (const float*)d_in[3];
    const float* w_hh   = (const float*)d_in[4];
    const float* b_ih   = (const float*)d_in[5];
    const float* b_hh   = (const float*)d_in[6];
    const float* out_W  = (const float*)d_in[7];
    const float* out_b  = (const float*)d_in[8];
    float* out = (float*)d_out;

    float *xg;
    __nv_bfloat16 *yhi, *ylo, *hhi, *hlo, *wih_hi, *wih_lo, *whh_hi, *whh_lo;
    cudaGetSymbolAddress((void**)&xg,     g_xg);
    cudaGetSymbolAddress((void**)&yhi,    g_y_hi);
    cudaGetSymbolAddress((void**)&ylo,    g_y_lo);
    cudaGetSymbolAddress((void**)&hhi,    g_h_hi);
    cudaGetSymbolAddress((void**)&hlo,    g_h_lo);
    cudaGetSymbolAddress((void**)&wih_hi, g_wih_hi);
    cudaGetSymbolAddress((void**)&wih_lo, g_wih_lo);
    cudaGetSymbolAddress((void**)&whh_hi, g_whh_hi);
    cudaGetSymbolAddress((void**)&whh_lo, g_whh_lo);

    cudaFuncSetAttribute(gru_layer_mma,
                         cudaFuncAttributeMaxDynamicSharedMemorySize, GRU_SMEM);

    const int M = LSEQ * NB;

    // 0) split weights to bf16 hi/lo
    split_kernel<<<4096, 256>>>(w_ih, wih_hi, wih_lo, NL * H3 * EDIM);
    split_kernel<<<4096, 256>>>(w_hh, whh_hi, whh_lo, NL * H3 * HDIM);

    // 1) embedding -> y (hi/lo)
    {
        dim3 grid(M, EDIM / 256);
        embed_kernel<<<grid, 256>>>(inputs, emb_W, emb_b, yhi, ylo);
    }

    for (int l = 0; l < NL; l++) {
        // 2a) input projection: xg = y @ w_ih[l]^T + b_ih[l]  (tensor cores)
        {
            dim3 grid(H3 / 64, M / 128);
            gemm_xg_mma<<<grid, 256>>>(yhi, ylo,
                                       wih_hi + (size_t)l * H3 * EDIM,
                                       wih_lo + (size_t)l * H3 * EDIM,
                                       b_ih + (size_t)l * H3,
                                       xg);
        }
        // 2b) persistent tensor-core recurrence (writes y in place)
        gru_layer_mma<<<GRU_BLOCKS, 128, GRU_SMEM>>>(
            xg,
            whh_hi + (size_t)l * H3 * HDIM,
            whh_lo + (size_t)l * H3 * HDIM,
            b_hh + (size_t)l * H3,
            hhi, hlo, yhi, ylo);
    }

    // 3) output projection
    outproj_kernel<<<M, 256>>>(yhi, ylo, out_W, out_b, out);

    (void)in_sizes; (void)n_in; (void)out_size;
}

// round 4
// speedup vs baseline: 2.4735x; 1.2183x over previous
#include <cuda_runtime.h>
#include <cuda_bf16.h>
#include <math.h>
#include <stdint.h>

#define LSEQ 512
#define NB   64
#define KIN  38
#define EDIM 1024
#define HDIM 1024
#define NL   3
#define NC   38
#define H3   (3*HDIM)

#define GRU_BLOCKS 128
#define WS_LD 1032
#define HS_LD 264
#define GRU_SMEM ((2*24*WS_LD + 2*64*HS_LD) * 2)

// ---------------- scratch (device globals; no allocations allowed) ----------
__device__ __align__(16) float         g_xg[(size_t)LSEQ * NB * H3];
__device__ __align__(16) __nv_bfloat16 g_y_hi[(size_t)LSEQ * NB * EDIM];
__device__ __align__(16) __nv_bfloat16 g_y_lo[(size_t)LSEQ * NB * EDIM];
__device__ __align__(16) __nv_bfloat16 g_h_hi[2 * NB * HDIM];
__device__ __align__(16) __nv_bfloat16 g_h_lo[2 * NB * HDIM];
__device__ __align__(16) __nv_bfloat16 g_wih_hi[(size_t)NL * H3 * EDIM];
__device__ __align__(16) __nv_bfloat16 g_wih_lo[(size_t)NL * H3 * EDIM];
__device__ __align__(16) __nv_bfloat16 g_whh_hi[(size_t)NL * H3 * HDIM];
__device__ __align__(16) __nv_bfloat16 g_whh_lo[(size_t)NL * H3 * HDIM];

// barrier state: monotonic epochs, persists across launches
__device__ unsigned g_flags[GRU_BLOCKS];
__device__ unsigned g_gen;

__device__ __forceinline__ void flag_barrier(int bid, unsigned target) {
    __syncthreads();
    if (threadIdx.x == 0) {
        __threadfence();
        ((volatile unsigned*)g_flags)[bid] = target;
    }
    if (bid == 0 && threadIdx.x < 32) {
        bool done = false;
        while (!done) {
            bool ok = true;
#pragma unroll
            for (int q = 0; q < 4; q++) {
                unsigned v = ((volatile unsigned*)g_flags)[threadIdx.x + q * 32];
                if ((int)(v - target) < 0) ok = false;
            }
            done = __all_sync(0xffffffffu, ok);
        }
        if (threadIdx.x == 0) {
            __threadfence();
            *(volatile unsigned*)&g_gen = target;
        }
    }
    if (threadIdx.x == 0) {
        while ((int)(*(volatile unsigned*)&g_gen - target) < 0) {}
        __threadfence();
    }
    __syncthreads();
}

// ---------------- mma helpers ------------------------------------------------
__device__ __forceinline__ uint32_t smem_u32(const void* p) {
    return (uint32_t)__cvta_generic_to_shared(p);
}
__device__ __forceinline__ void ldsm_x4(uint32_t* r, uint32_t addr) {
    asm volatile("ldmatrix.sync.aligned.m8n8.x4.shared.b16 {%0,%1,%2,%3},[%4];"
                 : "=r"(r[0]), "=r"(r[1]), "=r"(r[2]), "=r"(r[3]) : "r"(addr));
}
__device__ __forceinline__ void mma16816(float* c, const uint32_t* a,
                                         uint32_t b0, uint32_t b1) {
    asm volatile(
        "mma.sync.aligned.m16n8k16.row.col.f32.bf16.bf16.f32 "
        "{%0,%1,%2,%3},{%4,%5,%6,%7},{%8,%9},{%0,%1,%2,%3};"
        : "+f"(c[0]), "+f"(c[1]), "+f"(c[2]), "+f"(c[3])
        : "r"(a[0]), "r"(a[1]), "r"(a[2]), "r"(a[3]), "r"(b0), "r"(b1));
}
__device__ __forceinline__ void split2(float x, __nv_bfloat16& hi, __nv_bfloat16& lo) {
    hi = __float2bfloat16(x);
    lo = __float2bfloat16(x - __bfloat162float(hi));
}
__device__ __forceinline__ float sigmoidf_(float x) {
    return 1.f / (1.f + expf(-x));
}

// ---------------- weight split ----------------------------------------------
__global__ void split_kernel(const float* __restrict__ src,
                             __nv_bfloat16* __restrict__ hi,
                             __nv_bfloat16* __restrict__ lo, int n) {
    for (int i = blockIdx.x * 256 + threadIdx.x; i < n; i += gridDim.x * 256) {
        float x = src[i];
        __nv_bfloat16 h = __float2bfloat16(x);
        hi[i] = h;
        lo[i] = __float2bfloat16(x - __bfloat162float(h));
    }
}

// ---------------- embedding ---------------------------------------------------
__global__ void embed_kernel(const float* __restrict__ in,
                             const float* __restrict__ W,
                             const float* __restrict__ b,
                             __nv_bfloat16* __restrict__ yhi,
                             __nv_bfloat16* __restrict__ ylo) {
    int ln = blockIdx.x;
    int e  = blockIdx.y * 256 + threadIdx.x;
    __shared__ float xs[KIN];
    if (threadIdx.x < KIN) xs[threadIdx.x] = in[(size_t)ln * KIN + threadIdx.x];
    __syncthreads();
    float acc = b[e];
    const float* w = W + (size_t)e * KIN;
#pragma unroll
    for (int k = 0; k < KIN; k++) acc = fmaf(xs[k], w[k], acc);
    __nv_bfloat16 hh, hl;
    split2(acc, hh, hl);
    yhi[(size_t)ln * EDIM + e] = hh;
    ylo[(size_t)ln * EDIM + e] = hl;
}

// ---------------- bf16-split MMA GEMM (input projections) --------------------
__global__ void __launch_bounds__(256)
gemm_xg_mma(const __nv_bfloat16* __restrict__ Ahi,
            const __nv_bfloat16* __restrict__ Alo,
            const __nv_bfloat16* __restrict__ Bhi,
            const __nv_bfloat16* __restrict__ Blo,
            const float* __restrict__ bias,
            float* __restrict__ C) {
    __shared__ __nv_bfloat16 sA[2][128][40];
    __shared__ __nv_bfloat16 sB[2][64][40];
    const int tid = threadIdx.x, lane = tid & 31, warp = tid >> 5;
    const int wm = warp >> 1, wn = warp & 1;
    const int bm = blockIdx.y * 128, bn = blockIdx.x * 64;

    float c[2][4][4];
#pragma unroll
    for (int m = 0; m < 2; m++)
#pragma unroll
        for (int n = 0; n < 4; n++)
#pragma unroll
            for (int q = 0; q < 4; q++) c[m][n][q] = 0.f;

    for (int k0 = 0; k0 < EDIM; k0 += 32) {
        __syncthreads();
        for (int i = tid; i < 512; i += 256) {
            int r = i >> 2, cv = i & 3;
            *(uint4*)&sA[0][r][cv * 8] = *(const uint4*)(Ahi + (size_t)(bm + r) * EDIM + k0 + cv * 8);
            *(uint4*)&sA[1][r][cv * 8] = *(const uint4*)(Alo + (size_t)(bm + r) * EDIM + k0 + cv * 8);
        }
        if (tid < 256) {
            int r = tid >> 2, cv = tid & 3;
            *(uint4*)&sB[0][r][cv * 8] = *(const uint4*)(Bhi + (size_t)(bn + r) * EDIM + k0 + cv * 8);
            *(uint4*)&sB[1][r][cv * 8] = *(const uint4*)(Blo + (size_t)(bn + r) * EDIM + k0 + cv * 8);
        }
        __syncthreads();

        uint32_t a[2][2][2][4];
#pragma unroll
        for (int s = 0; s < 2; s++)
#pragma unroll
            for (int m = 0; m < 2; m++) {
                int arow = wm * 32 + m * 16 + (lane & 15);
                int acol = (lane >> 4) * 8;
                uint32_t ad = smem_u32(&sA[s][arow][acol]);
                ldsm_x4(a[s][m][0], ad);
                ldsm_x4(a[s][m][1], ad + 32);
            }
        uint32_t bf[2][4][4];
#pragma unroll
        for (int s = 0; s < 2; s++)
#pragma unroll
            for (int n = 0; n < 4; n++) {
                int brow = wn * 32 + n * 8 + (lane & 7);
                int bcol = (lane >> 3) * 8;
                ldsm_x4(bf[s][n], smem_u32(&sB[s][brow][bcol]));
            }
#pragma unroll
        for (int m = 0; m < 2; m++)
#pragma unroll
            for (int n = 0; n < 4; n++)
#pragma unroll
                for (int k = 0; k < 2; k++) {
                    mma16816(c[m][n], a[0][m][k], bf[0][n][k * 2], bf[0][n][k * 2 + 1]);
                    mma16816(c[m][n], a[0][m][k], bf[1][n][k * 2], bf[1][n][k * 2 + 1]);
                    mma16816(c[m][n], a[1][m][k], bf[0][n][k * 2], bf[0][n][k * 2 + 1]);
                }
    }

#pragma unroll
    for (int m = 0; m < 2; m++) {
        int row0 = bm + wm * 32 + m * 16 + (lane >> 2);
#pragma unroll
        for (int n = 0; n < 4; n++) {
            int col = bn + wn * 32 + n * 8 + (lane & 3) * 2;
            float2 bb = *(const float2*)(bias + col);
            float2 v0 = make_float2(c[m][n][0] + bb.x, c[m][n][1] + bb.y);
            float2 v1 = make_float2(c[m][n][2] + bb.x, c[m][n][3] + bb.y);
            *(float2*)(C + (size_t)row0 * H3 + col) = v0;
            *(float2*)(C + (size_t)(row0 + 8) * H3 + col) = v1;
        }
    }
}

// ---------------- persistent GRU layer: 256 threads, 4m x 2k warps -----------
__global__ void __launch_bounds__(256, 1)
gru_layer_mma(const float* __restrict__ xg,
              const __nv_bfloat16* __restrict__ whh_hi,
              const __nv_bfloat16* __restrict__ whh_lo,
              const float* __restrict__ bhh,
              __nv_bfloat16* __restrict__ hhi,
              __nv_bfloat16* __restrict__ hlo,
              __nv_bfloat16* __restrict__ yhi,
              __nv_bfloat16* __restrict__ ylo,
              unsigned epoch0) {
    extern __shared__ __nv_bfloat16 sm[];
    __nv_bfloat16* ws_hi = sm;                      // [24][WS_LD]
    __nv_bfloat16* ws_lo = ws_hi + 24 * WS_LD;
    __nv_bfloat16* hs_hi = ws_lo + 24 * WS_LD;      // [64][HS_LD], 256-col chunk
    __nv_bfloat16* hs_lo = hs_hi + 64 * HS_LD;
    float*         red    = (float*)hs_hi;          // reuse: 4*32*12 floats
    __nv_bfloat16* sm_out = hs_hi + 4096;           // reuse: 2*64*8 bf16 @ 8KB

    const int tid  = threadIdx.x;
    const int lane = tid & 31, warp = tid >> 5;
    const int wm = warp & 3, wk = warp >> 2;
    const int bid = blockIdx.x;
    const int j0 = bid * 8;

    // W tile -> smem
    for (int i = tid; i < 24 * 128; i += 256) {
        int r = i >> 7, v = i & 127;
        int grow = (r >> 3) * HDIM + j0 + (r & 7);
        *(uint4*)&ws_hi[r * WS_LD + v * 8] = *(const uint4*)(whh_hi + (size_t)grow * HDIM + v * 8);
        *(uint4*)&ws_lo[r * WS_LD + v * 8] = *(const uint4*)(whh_lo + (size_t)grow * HDIM + v * 8);
    }
    // zero h slot 0: block zeros its 512-element slice
    if (tid < 128) {
        int base = bid * 512 + tid * 4;
        uint2 z = make_uint2(0u, 0u);
        *(uint2*)&hhi[base] = z;
        *(uint2*)&hlo[base] = z;
    }

    unsigned epoch = epoch0;
    flag_barrier(bid, ++epoch);

    for (int t = 0; t < LSEQ; t++) {
        const __nv_bfloat16* hin_hi = hhi + (t & 1) * (NB * HDIM);
        const __nv_bfloat16* hin_lo = hlo + (t & 1) * (NB * HDIM);
        __nv_bfloat16* hout_hi = hhi + ((t + 1) & 1) * (NB * HDIM);
        __nv_bfloat16* hout_lo = hlo + ((t + 1) & 1) * (NB * HDIM);
        const float* xg_t = xg + (size_t)t * NB * H3;

        // prefetch epilogue operands (wk==0 warps do gates)
        float xr_[4], xz_[4], xn_[4], hp_[4];
        if (wk == 0) {
#pragma unroll
            for (int q = 0; q < 4; q++) {
                int b  = wm * 16 + (lane >> 2) + (q >> 1) * 8;
                int ja = j0 + (lane & 3) * 2 + (q & 1);
                const float* xr = xg_t + (size_t)b * H3 + ja;
                xr_[q] = xr[0];
                xz_[q] = xr[HDIM];
                xn_[q] = xr[2 * HDIM];
                hp_[q] = __bfloat162float(hin_hi[b * HDIM + ja]) +
                         __bfloat162float(hin_lo[b * HDIM + ja]);
            }
        }

        float c[3][4];
#pragma unroll
        for (int i = 0; i < 3; i++)
#pragma unroll
            for (int q = 0; q < 4; q++) c[i][q] = 0.f;

        for (int kc = 0; kc < 4; kc++) {
            const int k0 = kc * 256;
            __syncthreads();
            for (int i = tid; i < 2048; i += 256) {
                int rw = i >> 5, cv = (i & 31) * 8;
                *(uint4*)&hs_hi[rw * HS_LD + cv] = *(const uint4*)(hin_hi + rw * HDIM + k0 + cv);
                *(uint4*)&hs_lo[rw * HS_LD + cv] = *(const uint4*)(hin_lo + rw * HDIM + k0 + cv);
            }
            __syncthreads();
#pragma unroll
            for (int k32 = 0; k32 < 4; k32++) {
                const int lc = wk * 128 + k32 * 32;
                uint32_t a_hi[2][4], a_lo[2][4];
                {
                    int arow = wm * 16 + (lane & 15);
                    int acol = lc + (lane >> 4) * 8;
                    uint32_t ah = smem_u32(&hs_hi[arow * HS_LD + acol]);
                    uint32_t al = smem_u32(&hs_lo[arow * HS_LD + acol]);
                    ldsm_x4(a_hi[0], ah);  ldsm_x4(a_hi[1], ah + 32);
                    ldsm_x4(a_lo[0], al);  ldsm_x4(a_lo[1], al + 32);
                }
                uint32_t b_hi[3][4], b_lo[3][4];
                int bkcol = k0 + lc + (lane >> 3) * 8;
#pragma unroll
                for (int n8 = 0; n8 < 3; n8++) {
                    int brow = n8 * 8 + (lane & 7);
                    ldsm_x4(b_hi[n8], smem_u32(&ws_hi[brow * WS_LD + bkcol]));
                    ldsm_x4(b_lo[n8], smem_u32(&ws_lo[brow * WS_LD + bkcol]));
                }
#pragma unroll
                for (int n8 = 0; n8 < 3; n8++)
#pragma unroll
                    for (int k = 0; k < 2; k++) {
                        mma16816(c[n8], a_hi[k], b_hi[n8][k * 2], b_hi[n8][k * 2 + 1]);
                        mma16816(c[n8], a_hi[k], b_lo[n8][k * 2], b_lo[n8][k * 2 + 1]);
                        mma16816(c[n8], a_lo[k], b_hi[n8][k * 2], b_hi[n8][k * 2 + 1]);
                    }
            }
        }

        // combine k-halves
        __syncthreads();
        if (wk == 1) {
            float* rp = red + ((size_t)wm * 32 + lane) * 12;
#pragma unroll
            for (int i = 0; i < 3; i++)
#pragma unroll
                for (int q = 0; q < 4; q++) rp[i * 4 + q] = c[i][q];
        }
        __syncthreads();
        if (wk == 0) {
            const float* rp = red + ((size_t)wm * 32 + lane) * 12;
#pragma unroll
            for (int q = 0; q < 4; q++) {
                int jj = (lane & 3) * 2 + (q & 1);
                int ja = j0 + jj;
                int b  = wm * 16 + (lane >> 2) + (q >> 1) * 8;
                float hr = c[0][q] + rp[0 * 4 + q] + bhh[ja];
                float hz = c[1][q] + rp[1 * 4 + q] + bhh[HDIM + ja];
                float hn = c[2][q] + rp[2 * 4 + q] + bhh[2 * HDIM + ja];
                float r = sigmoidf_(xr_[q] + hr);
                float z = sigmoidf_(xz_[q] + hz);
                float n = tanhf(xn_[q] + r * hn);
                float hnew = (1.f - z) * n + z * hp_[q];
                __nv_bfloat16 hh, hl;
                split2(hnew, hh, hl);
                sm_out[b * 8 + jj] = hh;
                sm_out[512 + b * 8 + jj] = hl;
            }
        }
        __syncthreads();
        if (tid < 128) {
            int b = tid & 63, arr = tid >> 6;
            uint4 v = *(const uint4*)&sm_out[arr * 512 + b * 8];
            __nv_bfloat16* hdst = (arr == 0 ? hout_hi : hout_lo);
            __nv_bfloat16* ydst = (arr == 0 ? yhi : ylo);
            *(uint4*)&hdst[b * HDIM + j0] = v;
            *(uint4*)&ydst[(size_t)t * NB * HDIM + b * HDIM + j0] = v;
        }

        flag_barrier(bid, ++epoch);
    }
}

// ---------------- output projection ------------------------------------------
__global__ void outproj_kernel(const __nv_bfloat16* __restrict__ xhi,
                               const __nv_bfloat16* __restrict__ xlo,
                               const float* __restrict__ W,
                               const float* __restrict__ b,
                               float* __restrict__ out) {
    int ln = blockIdx.x;
    __shared__ float xs[HDIM];
    const __nv_bfloat16* xh = xhi + (size_t)ln * HDIM;
    const __nv_bfloat16* xl = xlo + (size_t)ln * HDIM;
    for (int k = threadIdx.x; k < HDIM; k += 256)
        xs[k] = __bfloat162float(xh[k]) + __bfloat162float(xl[k]);
    __syncthreads();
    int warp = threadIdx.x >> 5, lane = threadIdx.x & 31;
    for (int c = warp; c < NC; c += 8) {
        const float* w = W + (size_t)c * HDIM;
        float acc = 0.f;
        for (int k = lane; k < HDIM; k += 32) acc = fmaf(xs[k], w[k], acc);
#pragma unroll
        for (int o = 16; o; o >>= 1) acc += __shfl_xor_sync(0xffffffffu, acc, o);
        if (lane == 0) out[(size_t)ln * NC + c] = acc + b[c];
    }
}

// ---------------- orchestration ---------------------------------------------
static unsigned h_epoch = 0;

extern "C" void kernel_launch(void* const* d_in, const int* in_sizes, int n_in,
                              void* d_out, int out_size) {
    const float* inputs = (const float*)d_in[0];
    const float* emb_W  = (const float*)d_in[1];
    const float* emb_b  = (const float*)d_in[2];
    const float* w_ih   = (const float*)d_in[3];
    const float* w_hh   = (const float*)d_in[4];
    const float* b_ih   = (const float*)d_in[5];
    const float* b_hh   = (const float*)d_in[6];
    const float* out_W  = (const float*)d_in[7];
    const float* out_b  = (const float*)d_in[8];
    float* out = (float*)d_out;

    float *xg;
    __nv_bfloat16 *yhi, *ylo, *hhi, *hlo, *wih_hi, *wih_lo, *whh_hi, *whh_lo;
    cudaGetSymbolAddress((void**)&xg,     g_xg);
    cudaGetSymbolAddress((void**)&yhi,    g_y_hi);
    cudaGetSymbolAddress((void**)&ylo,    g_y_lo);
    cudaGetSymbolAddress((void**)&hhi,    g_h_hi);
    cudaGetSymbolAddress((void**)&hlo,    g_h_lo);
    cudaGetSymbolAddress((void**)&wih_hi, g_wih_hi);
    cudaGetSymbolAddress((void**)&wih_lo, g_wih_lo);
    cudaGetSymbolAddress((void**)&whh_hi, g_whh_hi);
    cudaGetSymbolAddress((void**)&whh_lo, g_whh_lo);

    cudaFuncSetAttribute(gru_layer_mma,
                         cudaFuncAttributeMaxDynamicSharedMemorySize, GRU_SMEM);

    const int M = LSEQ * NB;

    split_kernel<<<4096, 256>>>(w_ih, wih_hi, wih_lo, NL * H3 * EDIM);
    split_kernel<<<4096, 256>>>(w_hh, whh_hi, whh_lo, NL * H3 * HDIM);

    {
        dim3 grid(M, EDIM / 256);
        embed_kernel<<<grid, 256>>>(inputs, emb_W, emb_b, yhi, ylo);
    }

    for (int l = 0; l < NL; l++) {
        {
            dim3 grid(H3 / 64, M / 128);
            gemm_xg_mma<<<grid, 256>>>(yhi, ylo,
                                       wih_hi + (size_t)l * H3 * EDIM,
                                       wih_lo + (size_t)l * H3 * EDIM,
                                       b_ih + (size_t)l * H3,
                                       xg);
        }
        gru_layer_mma<<<GRU_BLOCKS, 256, GRU_SMEM>>>(
            xg,
            whh_hi + (size_t)l * H3 * HDIM,
            whh_lo + (size_t)l * H3 * HDIM,
            b_hh + (size_t)l * H3,
            hhi, hlo, yhi, ylo,
            h_epoch);
        h_epoch += LSEQ + 1;
    }

    outproj_kernel<<<M, 256>>>(yhi, ylo, out_W, out_b, out);

    (void)in_sizes; (void)n_in; (void)out_size;
}

// round 6
// speedup vs baseline: 2.7657x; 1.1181x over previous
#include <cuda_runtime.h>
#include <cuda_bf16.h>
#include <math.h>
#include <stdint.h>

#define LSEQ 512
#define NB   64
#define KIN  38
#define EDIM 1024
#define HDIM 1024
#define NL   3
#define NC   38
#define H3   (3*HDIM)

#define GRU_BLOCKS 128
#define WS_LD 1032

// smem byte offsets for gru kernel
#define WS_HI_OFF 0
#define WS_LO_OFF 49536                      // 24*1032*2
#define HB_OFF    99072                      // 4 bufs x (64*136*2 = 17408)
#define RED_OFF   168704                     // 4*32*12 floats = 6144
#define SMOUT_OFF 174848                     // 2*64*8 bf16 = 2048
#define GRU_SMEM  176896

// ---------------- scratch (device globals; no allocations allowed) ----------
__device__ __align__(16) float         g_xg[(size_t)LSEQ * NB * H3];
__device__ __align__(16) __nv_bfloat16 g_y_hi[(size_t)LSEQ * NB * EDIM];
__device__ __align__(16) __nv_bfloat16 g_y_lo[(size_t)LSEQ * NB * EDIM];
__device__ __align__(16) __nv_bfloat16 g_h_hi[2 * NB * HDIM];
__device__ __align__(16) __nv_bfloat16 g_h_lo[2 * NB * HDIM];
__device__ __align__(16) __nv_bfloat16 g_wih_hi[(size_t)NL * H3 * EDIM];
__device__ __align__(16) __nv_bfloat16 g_wih_lo[(size_t)NL * H3 * EDIM];
__device__ __align__(16) __nv_bfloat16 g_whh_hi[(size_t)NL * H3 * HDIM];
__device__ __align__(16) __nv_bfloat16 g_whh_lo[(size_t)NL * H3 * HDIM];

// barrier flags (monotonic; generation derived from flag value => replay-safe)
__device__ unsigned g_flags[GRU_BLOCKS];

__device__ __forceinline__ void flag_barrier(int bid, unsigned target) {
    __syncthreads();
    if (threadIdx.x == 0) {
        __threadfence();
        ((volatile unsigned*)g_flags)[bid] = target;
    }
    if (threadIdx.x < 32) {
        bool done = false;
        while (!done) {
            bool ok = true;
#pragma unroll
            for (int q = 0; q < 4; q++) {
                unsigned v = ((volatile unsigned*)g_flags)[threadIdx.x + q * 32];
                if ((int)(v - target) < 0) ok = false;
            }
            done = __all_sync(0xffffffffu, ok);
        }
    }
    __syncthreads();
}

// ---------------- helpers ------------------------------------------------------
__device__ __forceinline__ uint32_t smem_u32(const void* p) {
    return (uint32_t)__cvta_generic_to_shared(p);
}
__device__ __forceinline__ void ldsm_x4(uint32_t* r, uint32_t addr) {
    asm volatile("ldmatrix.sync.aligned.m8n8.x4.shared.b16 {%0,%1,%2,%3},[%4];"
                 : "=r"(r[0]), "=r"(r[1]), "=r"(r[2]), "=r"(r[3]) : "r"(addr));
}
__device__ __forceinline__ void mma16816(float* c, const uint32_t* a,
                                         uint32_t b0, uint32_t b1) {
    asm volatile(
        "mma.sync.aligned.m16n8k16.row.col.f32.bf16.bf16.f32 "
        "{%0,%1,%2,%3},{%4,%5,%6,%7},{%8,%9},{%0,%1,%2,%3};"
        : "+f"(c[0]), "+f"(c[1]), "+f"(c[2]), "+f"(c[3])
        : "r"(a[0]), "r"(a[1]), "r"(a[2]), "r"(a[3]), "r"(b0), "r"(b1));
}
__device__ __forceinline__ void cp_async16(uint32_t daddr, const void* src) {
    asm volatile("cp.async.cg.shared.global [%0], [%1], 16;"
                 :: "r"(daddr), "l"(__cvta_generic_to_global(src)));
}
__device__ __forceinline__ void split2(float x, __nv_bfloat16& hi, __nv_bfloat16& lo) {
    hi = __float2bfloat16(x);
    lo = __float2bfloat16(x - __bfloat162float(hi));
}
__device__ __forceinline__ float sigmoidf_(float x) {
    return 1.f / (1.f + expf(-x));
}

// ---------------- weight split ----------------------------------------------
__global__ void split_kernel(const float* __restrict__ src,
                             __nv_bfloat16* __restrict__ hi,
                             __nv_bfloat16* __restrict__ lo, int n) {
    for (int i = blockIdx.x * 256 + threadIdx.x; i < n; i += gridDim.x * 256) {
        float x = src[i];
        __nv_bfloat16 h = __float2bfloat16(x);
        hi[i] = h;
        lo[i] = __float2bfloat16(x - __bfloat162float(h));
    }
}

// ---------------- embedding ---------------------------------------------------
__global__ void embed_kernel(const float* __restrict__ in,
                             const float* __restrict__ W,
                             const float* __restrict__ b,
                             __nv_bfloat16* __restrict__ yhi,
                             __nv_bfloat16* __restrict__ ylo) {
    int ln = blockIdx.x;
    int e  = blockIdx.y * 256 + threadIdx.x;
    __shared__ float xs[KIN];
    if (threadIdx.x < KIN) xs[threadIdx.x] = in[(size_t)ln * KIN + threadIdx.x];
    __syncthreads();
    float acc = b[e];
    const float* w = W + (size_t)e * KIN;
#pragma unroll
    for (int k = 0; k < KIN; k++) acc = fmaf(xs[k], w[k], acc);
    __nv_bfloat16 hh, hl;
    split2(acc, hh, hl);
    yhi[(size_t)ln * EDIM + e] = hh;
    ylo[(size_t)ln * EDIM + e] = hl;
}

// ---------------- bf16-split MMA GEMM (input projections) --------------------
__global__ void __launch_bounds__(256)
gemm_xg_mma(const __nv_bfloat16* __restrict__ Ahi,
            const __nv_bfloat16* __restrict__ Alo,
            const __nv_bfloat16* __restrict__ Bhi,
            const __nv_bfloat16* __restrict__ Blo,
            const float* __restrict__ bias,
            float* __restrict__ C) {
    __shared__ __nv_bfloat16 sA[2][128][40];
    __shared__ __nv_bfloat16 sB[2][64][40];
    const int tid = threadIdx.x, lane = tid & 31, warp = tid >> 5;
    const int wm = warp >> 1, wn = warp & 1;
    const int bm = blockIdx.y * 128, bn = blockIdx.x * 64;

    float c[2][4][4];
#pragma unroll
    for (int m = 0; m < 2; m++)
#pragma unroll
        for (int n = 0; n < 4; n++)
#pragma unroll
            for (int q = 0; q < 4; q++) c[m][n][q] = 0.f;

    for (int k0 = 0; k0 < EDIM; k0 += 32) {
        __syncthreads();
        for (int i = tid; i < 512; i += 256) {
            int r = i >> 2, cv = i & 3;
            *(uint4*)&sA[0][r][cv * 8] = *(const uint4*)(Ahi + (size_t)(bm + r) * EDIM + k0 + cv * 8);
            *(uint4*)&sA[1][r][cv * 8] = *(const uint4*)(Alo + (size_t)(bm + r) * EDIM + k0 + cv * 8);
        }
        if (tid < 256) {
            int r = tid >> 2, cv = tid & 3;
            *(uint4*)&sB[0][r][cv * 8] = *(const uint4*)(Bhi + (size_t)(bn + r) * EDIM + k0 + cv * 8);
            *(uint4*)&sB[1][r][cv * 8] = *(const uint4*)(Blo + (size_t)(bn + r) * EDIM + k0 + cv * 8);
        }
        __syncthreads();

        uint32_t a[2][2][2][4];
#pragma unroll
        for (int s = 0; s < 2; s++)
#pragma unroll
            for (int m = 0; m < 2; m++) {
                int arow = wm * 32 + m * 16 + (lane & 15);
                int acol = (lane >> 4) * 8;
                uint32_t ad = smem_u32(&sA[s][arow][acol]);
                ldsm_x4(a[s][m][0], ad);
                ldsm_x4(a[s][m][1], ad + 32);
            }
        uint32_t bf[2][4][4];
#pragma unroll
        for (int s = 0; s < 2; s++)
#pragma unroll
            for (int n = 0; n < 4; n++) {
                int brow = wn * 32 + n * 8 + (lane & 7);
                int bcol = (lane >> 3) * 8;
                ldsm_x4(bf[s][n], smem_u32(&sB[s][brow][bcol]));
            }
#pragma unroll
        for (int m = 0; m < 2; m++)
#pragma unroll
            for (int n = 0; n < 4; n++)
#pragma unroll
                for (int k = 0; k < 2; k++) {
                    mma16816(c[m][n], a[0][m][k], bf[0][n][k * 2], bf[0][n][k * 2 + 1]);
                    mma16816(c[m][n], a[0][m][k], bf[1][n][k * 2], bf[1][n][k * 2 + 1]);
                    mma16816(c[m][n], a[1][m][k], bf[0][n][k * 2], bf[0][n][k * 2 + 1]);
                }
    }

#pragma unroll
    for (int m = 0; m < 2; m++) {
        int row0 = bm + wm * 32 + m * 16 + (lane >> 2);
#pragma unroll
        for (int n = 0; n < 4; n++) {
            int col = bn + wn * 32 + n * 8 + (lane & 3) * 2;
            float2 bb = *(const float2*)(bias + col);
            float2 v0 = make_float2(c[m][n][0] + bb.x, c[m][n][1] + bb.y);
            float2 v1 = make_float2(c[m][n][2] + bb.x, c[m][n][3] + bb.y);
            *(float2*)(C + (size_t)row0 * H3 + col) = v0;
            *(float2*)(C + (size_t)(row0 + 8) * H3 + col) = v1;
        }
    }
}

// ---------------- persistent GRU layer: cp.async double-buffered -------------
// 256 threads (8 warps: 4 wm x 2 wk). Block owns 8 hidden cols (24 W rows).
// W (hi/lo) resident in smem for all 512 steps. h staged per step in 8
// double-buffered 128-col chunks via cp.async.cg (bypasses L1).
__global__ void __launch_bounds__(256, 1)
gru_layer_mma(const float* __restrict__ xg,
              const __nv_bfloat16* __restrict__ whh_hi,
              const __nv_bfloat16* __restrict__ whh_lo,
              const float* __restrict__ bhh,
              __nv_bfloat16* __restrict__ hhi,
              __nv_bfloat16* __restrict__ hlo,
              __nv_bfloat16* __restrict__ yhi,
              __nv_bfloat16* __restrict__ ylo) {
    extern __shared__ __align__(16) char smem[];
    __nv_bfloat16* ws_hi  = (__nv_bfloat16*)(smem + WS_HI_OFF);
    __nv_bfloat16* ws_lo  = (__nv_bfloat16*)(smem + WS_LO_OFF);
    float*         red    = (float*)(smem + RED_OFF);
    __nv_bfloat16* sm_out = (__nv_bfloat16*)(smem + SMOUT_OFF);
    const uint32_t smem_base = smem_u32(smem);
    const uint32_t hb_base = smem_base + HB_OFF;

    const int tid  = threadIdx.x;
    const int lane = tid & 31, warp = tid >> 5;
    const int wm = warp & 3, wk = warp >> 2;
    const int bid = blockIdx.x;
    const int j0 = bid * 8;

    // W tile -> smem (rows r = g*8+jj -> global row g*HDIM + j0 + jj)
    for (int i = tid; i < 24 * 128; i += 256) {
        int r = i >> 7, v = i & 127;
        int grow = (r >> 3) * HDIM + j0 + (r & 7);
        *(uint4*)&ws_hi[r * WS_LD + v * 8] = *(const uint4*)(whh_hi + (size_t)grow * HDIM + v * 8);
        *(uint4*)&ws_lo[r * WS_LD + v * 8] = *(const uint4*)(whh_lo + (size_t)grow * HDIM + v * 8);
    }
    // zero h slot 0 (block's slice)
    if (tid < 128) {
        int base = bid * 512 + tid * 4;
        *(uint2*)&hhi[base] = make_uint2(0u, 0u);
        *(uint2*)&hlo[base] = make_uint2(0u, 0u);
    }

    unsigned bar_t = ((volatile unsigned*)g_flags)[bid];
    flag_barrier(bid, ++bar_t);

    for (int t = 0; t < LSEQ; t++) {
        const __nv_bfloat16* hin_hi = hhi + (t & 1) * (NB * HDIM);
        const __nv_bfloat16* hin_lo = hlo + (t & 1) * (NB * HDIM);
        __nv_bfloat16* hout_hi = hhi + ((t + 1) & 1) * (NB * HDIM);
        __nv_bfloat16* hout_lo = hlo + ((t + 1) & 1) * (NB * HDIM);
        const float* xg_t = xg + (size_t)t * NB * H3;

        // kick off chunk 0 staging immediately
        {
#pragma unroll
            for (int q = 0; q < 8; q++) {
                int idx = q * 256 + tid;
                int s = idx >> 10, rem = idx & 1023;
                int r = rem >> 4, g = rem & 15;
                const __nv_bfloat16* src = (s ? hin_lo : hin_hi) + r * HDIM + g * 8;
                uint32_t dst = hb_base + (uint32_t)s * 17408u + ((uint32_t)r * 136u + g * 8u) * 2u;
                cp_async16(dst, src);
            }
            asm volatile("cp.async.commit_group;" ::: "memory");
        }

        // prefetch epilogue operands (wk==0 warps do gates)
        float xr_[4], xz_[4], xn_[4], hp_[4];
        if (wk == 0) {
#pragma unroll
            for (int q = 0; q < 4; q++) {
                int b  = wm * 16 + (lane >> 2) + (q >> 1) * 8;
                int ja = j0 + (lane & 3) * 2 + (q & 1);
                const float* xr = xg_t + (size_t)b * H3 + ja;
                xr_[q] = xr[0];
                xz_[q] = xr[HDIM];
                xn_[q] = xr[2 * HDIM];
                float hh = __bfloat162float(__ldcg(hin_hi + b * HDIM + ja));
                float hl = __bfloat162float(__ldcg(hin_lo + b * HDIM + ja));
                hp_[q] = hh + hl;
            }
        }

        float c[3][4];
#pragma unroll
        for (int i = 0; i < 3; i++)
#pragma unroll
            for (int q = 0; q < 4; q++) c[i][q] = 0.f;

        for (int ch = 0; ch < 8; ch++) {
            const int buf = ch & 1;
            // issue next chunk into other buffer
            if (ch < 7) {
                const int nc = ch + 1, nbuf = nc & 1;
#pragma unroll
                for (int q = 0; q < 8; q++) {
                    int idx = q * 256 + tid;
                    int s = idx >> 10, rem = idx & 1023;
                    int r = rem >> 4, g = rem & 15;
                    const __nv_bfloat16* src = (s ? hin_lo : hin_hi) + r * HDIM + nc * 128 + g * 8;
                    uint32_t dst = hb_base + (uint32_t)(nbuf * 2 + s) * 17408u +
                                   ((uint32_t)r * 136u + g * 8u) * 2u;
                    cp_async16(dst, src);
                }
                asm volatile("cp.async.commit_group;" ::: "memory");
                asm volatile("cp.async.wait_group 1;" ::: "memory");
            } else {
                asm volatile("cp.async.wait_group 0;" ::: "memory");
            }
            __syncthreads();

#pragma unroll
            for (int k32 = 0; k32 < 2; k32++) {
                uint32_t a_hi[2][4], a_lo[2][4];
                {
                    int arow = wm * 16 + (lane & 15);
                    int acol = wk * 64 + k32 * 32 + (lane >> 4) * 8;
                    uint32_t ah = hb_base + (uint32_t)(buf * 2 + 0) * 17408u +
                                  ((uint32_t)arow * 136u + acol) * 2u;
                    uint32_t al = hb_base + (uint32_t)(buf * 2 + 1) * 17408u +
                                  ((uint32_t)arow * 136u + acol) * 2u;
                    ldsm_x4(a_hi[0], ah);  ldsm_x4(a_hi[1], ah + 32);
                    ldsm_x4(a_lo[0], al);  ldsm_x4(a_lo[1], al + 32);
                }
                uint32_t b_hi[3][4], b_lo[3][4];
                int bkcol = ch * 128 + wk * 64 + k32 * 32 + (lane >> 3) * 8;
#pragma unroll
                for (int n8 = 0; n8 < 3; n8++) {
                    int brow = n8 * 8 + (lane & 7);
                    ldsm_x4(b_hi[n8], smem_u32(&ws_hi[brow * WS_LD + bkcol]));
                    ldsm_x4(b_lo[n8], smem_u32(&ws_lo[brow * WS_LD + bkcol]));
                }
#pragma unroll
                for (int n8 = 0; n8 < 3; n8++)
#pragma unroll
                    for (int k = 0; k < 2; k++) {
                        mma16816(c[n8], a_hi[k], b_hi[n8][k * 2], b_hi[n8][k * 2 + 1]);
                        mma16816(c[n8], a_hi[k], b_lo[n8][k * 2], b_lo[n8][k * 2 + 1]);
                        mma16816(c[n8], a_lo[k], b_hi[n8][k * 2], b_hi[n8][k * 2 + 1]);
                    }
            }
            __syncthreads();
        }

        // combine k-halves
        if (wk == 1) {
            float* rp = red + ((size_t)wm * 32 + lane) * 12;
#pragma unroll
            for (int i = 0; i < 3; i++)
#pragma unroll
                for (int q = 0; q < 4; q++) rp[i * 4 + q] = c[i][q];
        }
        __syncthreads();
        if (wk == 0) {
            const float* rp = red + ((size_t)wm * 32 + lane) * 12;
#pragma unroll
            for (int q = 0; q < 4; q++) {
                int jj = (lane & 3) * 2 + (q & 1);
                int ja = j0 + jj;
                int b  = wm * 16 + (lane >> 2) + (q >> 1) * 8;
                float hr = c[0][q] + rp[0 * 4 + q] + bhh[ja];
                float hz = c[1][q] + rp[1 * 4 + q] + bhh[HDIM + ja];
                float hn = c[2][q] + rp[2 * 4 + q] + bhh[2 * HDIM + ja];
                float r = sigmoidf_(xr_[q] + hr);
                float z = sigmoidf_(xz_[q] + hz);
                float n = tanhf(xn_[q] + r * hn);
                float hnew = (1.f - z) * n + z * hp_[q];
                __nv_bfloat16 hh, hl;
                split2(hnew, hh, hl);
                sm_out[b * 8 + jj] = hh;
                sm_out[512 + b * 8 + jj] = hl;
            }
        }
        __syncthreads();

        // store h_out (inter-block critical path), barrier, then y
        uint4 v;
        int b_ = tid & 63, arr_ = tid >> 6;
        if (tid < 128) {
            v = *(const uint4*)&sm_out[arr_ * 512 + b_ * 8];
            __nv_bfloat16* hdst = (arr_ == 0 ? hout_hi : hout_lo);
            *(uint4*)&hdst[b_ * HDIM + j0] = v;
        }

        flag_barrier(bid, ++bar_t);

        if (tid < 128) {
            __nv_bfloat16* ydst = (arr_ == 0 ? yhi : ylo);
            *(uint4*)&ydst[(size_t)t * NB * HDIM + b_ * HDIM + j0] = v;
        }
    }
}

// ---------------- output projection ------------------------------------------
__global__ void outproj_kernel(const __nv_bfloat16* __restrict__ xhi,
                               const __nv_bfloat16* __restrict__ xlo,
                               const float* __restrict__ W,
                               const float* __restrict__ b,
                               float* __restrict__ out) {
    int ln = blockIdx.x;
    __shared__ float xs[HDIM];
    const __nv_bfloat16* xh = xhi + (size_t)ln * HDIM;
    const __nv_bfloat16* xl = xlo + (size_t)ln * HDIM;
    for (int k = threadIdx.x; k < HDIM; k += 256)
        xs[k] = __bfloat162float(xh[k]) + __bfloat162float(xl[k]);
    __syncthreads();
    int warp = threadIdx.x >> 5, lane = threadIdx.x & 31;
    for (int c = warp; c < NC; c += 8) {
        const float* w = W + (size_t)c * HDIM;
        float acc = 0.f;
        for (int k = lane; k < HDIM; k += 32) acc = fmaf(xs[k], w[k], acc);
#pragma unroll
        for (int o = 16; o; o >>= 1) acc += __shfl_xor_sync(0xffffffffu, acc, o);
        if (lane == 0) out[(size_t)ln * NC + c] = acc + b[c];
    }
}

// ---------------- orchestration ---------------------------------------------
extern "C" void kernel_launch(void* const* d_in, const int* in_sizes, int n_in,
                              void* d_out, int out_size) {
    const float* inputs = (const float*)d_in[0];
    const float* emb_W  = (const float*)d_in[1];
    const float* emb_b  = (const float*)d_in[2];
    const float* w_ih   = (const float*)d_in[3];
    const float* w_hh   = (const float*)d_in[4];
    const float* b_ih   = (const float*)d_in[5];
    const float* b_hh   = (const float*)d_in[6];
    const float* out_W  = (const float*)d_in[7];
    const float* out_b  = (const float*)d_in[8];
    float* out = (float*)d_out;

    float *xg;
    __nv_bfloat16 *yhi, *ylo, *hhi, *hlo, *wih_hi, *wih_lo, *whh_hi, *whh_lo;
    cudaGetSymbolAddress((void**)&xg,     g_xg);
    cudaGetSymbolAddress((void**)&yhi,    g_y_hi);
    cudaGetSymbolAddress((void**)&ylo,    g_y_lo);
    cudaGetSymbolAddress((void**)&hhi,    g_h_hi);
    cudaGetSymbolAddress((void**)&hlo,    g_h_lo);
    cudaGetSymbolAddress((void**)&wih_hi, g_wih_hi);
    cudaGetSymbolAddress((void**)&wih_lo, g_wih_lo);
    cudaGetSymbolAddress((void**)&whh_hi, g_whh_hi);
    cudaGetSymbolAddress((void**)&whh_lo, g_whh_lo);

    cudaFuncSetAttribute(gru_layer_mma,
                         cudaFuncAttributeMaxDynamicSharedMemorySize, GRU_SMEM);

    const int M = LSEQ * NB;

    split_kernel<<<4096, 256>>>(w_ih, wih_hi, wih_lo, NL * H3 * EDIM);
    split_kernel<<<4096, 256>>>(w_hh, whh_hi, whh_lo, NL * H3 * HDIM);

    {
        dim3 grid(M, EDIM / 256);
        embed_kernel<<<grid, 256>>>(inputs, emb_W, emb_b, yhi, ylo);
    }

    for (int l = 0; l < NL; l++) {
        {
            dim3 grid(H3 / 64, M / 128);
            gemm_xg_mma<<<grid, 256>>>(yhi, ylo,
                                       wih_hi + (size_t)l * H3 * EDIM,
                                       wih_lo + (size_t)l * H3 * EDIM,
                                       b_ih + (size_t)l * H3,
                                       xg);
        }
        gru_layer_mma<<<GRU_BLOCKS, 256, GRU_SMEM>>>(
            xg,
            whh_hi + (size_t)l * H3 * HDIM,
            whh_lo + (size_t)l * H3 * HDIM,
            b_hh + (size_t)l * H3,
            hhi, hlo, yhi, ylo);
    }

    outproj_kernel<<<M, 256>>>(yhi, ylo, out_W, out_b, out);

    (void)in_sizes; (void)n_in; (void)out_size;
}

// round 7
// speedup vs baseline: 3.5294x; 1.2761x over previous
#include <cuda_runtime.h>
#include <cuda_bf16.h>
#include <math.h>
#include <stdint.h>

#define LSEQ 512
#define NB   64
#define KIN  38
#define EDIM 1024
#define HDIM 1024
#define NL   3
#define NC   38
#define H3   (3*HDIM)

#define GRU_BLOCKS 128
#define WS_LD 1032

// gru smem byte offsets
#define MB0_OFF   0
#define MB1_OFF   8
#define WS_HI_OFF 16
#define WS_LO_OFF (WS_HI_OFF + 24*WS_LD*2)     // 49552
#define HB_OFF    (WS_LO_OFF + 24*WS_LD*2)     // 99088
#define RED_OFF   (HB_OFF + 2*32768)           // 164624
#define SMOUT_OFF (RED_OFF + 6144)             // 170768
#define GRU_SMEM  (SMOUT_OFF + 2048)           // 172816

// h2 layout: [slot(2)][chunk(8)][split(2)][row(64)][col(128)] bf16,
// groups of 8 cols xor-swizzled by (row&7).
#define H2_SLOT 131072

// ---------------- scratch (device globals; no allocations allowed) ----------
__device__ __align__(16) float         g_xg[(size_t)LSEQ * NB * H3];
__device__ __align__(16) __nv_bfloat16 g_y_hi[(size_t)LSEQ * NB * EDIM];
__device__ __align__(16) __nv_bfloat16 g_y_lo[(size_t)LSEQ * NB * EDIM];
__device__ __align__(16) __nv_bfloat16 g_h2[2 * H2_SLOT];
__device__ __align__(16) __nv_bfloat16 g_wih_hi[(size_t)NL * H3 * EDIM];
__device__ __align__(16) __nv_bfloat16 g_wih_lo[(size_t)NL * H3 * EDIM];
__device__ __align__(16) __nv_bfloat16 g_whh_hi[(size_t)NL * H3 * HDIM];
__device__ __align__(16) __nv_bfloat16 g_whh_lo[(size_t)NL * H3 * HDIM];

// barrier flags (monotonic; generation derived from flag value => replay-safe)
__device__ unsigned g_flags[GRU_BLOCKS];

__device__ __forceinline__ void flag_barrier(int bid, unsigned target) {
    __syncthreads();
    if (threadIdx.x == 0) {
        __threadfence();
        ((volatile unsigned*)g_flags)[bid] = target;
    }
    if (threadIdx.x < 32) {
        bool done = false;
        while (!done) {
            bool ok = true;
#pragma unroll
            for (int q = 0; q < 4; q++) {
                unsigned v = ((volatile unsigned*)g_flags)[threadIdx.x + q * 32];
                if ((int)(v - target) < 0) ok = false;
            }
            done = __all_sync(0xffffffffu, ok);
        }
    }
    __syncthreads();
}

// ---------------- helpers ------------------------------------------------------
__device__ __forceinline__ uint32_t smem_u32(const void* p) {
    return (uint32_t)__cvta_generic_to_shared(p);
}
__device__ __forceinline__ void ldsm_x4(uint32_t* r, uint32_t addr) {
    asm volatile("ldmatrix.sync.aligned.m8n8.x4.shared.b16 {%0,%1,%2,%3},[%4];"
                 : "=r"(r[0]), "=r"(r[1]), "=r"(r[2]), "=r"(r[3]) : "r"(addr));
}
__device__ __forceinline__ void mma16816(float* c, const uint32_t* a,
                                         uint32_t b0, uint32_t b1) {
    asm volatile(
        "mma.sync.aligned.m16n8k16.row.col.f32.bf16.bf16.f32 "
        "{%0,%1,%2,%3},{%4,%5,%6,%7},{%8,%9},{%0,%1,%2,%3};"
        : "+f"(c[0]), "+f"(c[1]), "+f"(c[2]), "+f"(c[3])
        : "r"(a[0]), "r"(a[1]), "r"(a[2]), "r"(a[3]), "r"(b0), "r"(b1));
}
__device__ __forceinline__ void bulk_copy(uint32_t dst_smem, const void* src,
                                          uint32_t bytes, uint32_t mbar) {
    asm volatile(
        "cp.async.bulk.shared::cluster.global.mbarrier::complete_tx::bytes "
        "[%0], [%1], %2, [%3];"
        :: "r"(dst_smem), "l"(__cvta_generic_to_global(src)), "r"(bytes), "r"(mbar)
        : "memory");
}
#define MBARRIER_INIT(mb, cnt) \
    asm volatile("mbarrier.init.shared.b64 [%0], %1;" :: "r"((uint32_t)(mb)), "r"((uint32_t)(cnt)) : "memory")
#define MBARRIER_EXPECT_TX(mb, tx) \
    asm volatile("mbarrier.arrive.expect_tx.shared.b64 _, [%0], %1;" \
                 :: "r"((uint32_t)(mb)), "r"((uint32_t)(tx)) : "memory")
#define MBARRIER_WAIT_PARITY(mb, ph) do { \
    uint32_t _mb = (uint32_t)(mb), _ph = (uint32_t)(ph), _done; \
    asm volatile("{\n\t.reg .pred p;\n\t" \
        "mbarrier.try_wait.parity.acquire.cta.shared::cta.b64 p, [%1], %2;\n\t" \
        "selp.b32 %0, 1, 0, p;\n\t}" : "=r"(_done) : "r"(_mb), "r"(_ph) : "memory"); \
    if (!_done) { \
        asm volatile("{\n\t.reg .pred P1;\n\t" \
            "WAIT_LOOP_%=:\n\t" \
            "mbarrier.try_wait.parity.acquire.cta.shared::cta.b64 P1, [%0], %1, 0x989680;\n\t" \
            "@P1 bra.uni WAIT_DONE_%=;\n\tbra.uni WAIT_LOOP_%=;\n\tWAIT_DONE_%=:\n\t}" \
            :: "r"(_mb), "r"(_ph) : "memory"); \
    } \
} while (0)

__device__ __forceinline__ void split2(float x, __nv_bfloat16& hi, __nv_bfloat16& lo) {
    hi = __float2bfloat16(x);
    lo = __float2bfloat16(x - __bfloat162float(hi));
}
__device__ __forceinline__ float sigmoidf_(float x) {
    return 1.f / (1.f + expf(-x));
}

// ---------------- weight split ----------------------------------------------
__global__ void split_kernel(const float* __restrict__ src,
                             __nv_bfloat16* __restrict__ hi,
                             __nv_bfloat16* __restrict__ lo, int n) {
    for (int i = blockIdx.x * 256 + threadIdx.x; i < n; i += gridDim.x * 256) {
        float x = src[i];
        __nv_bfloat16 h = __float2bfloat16(x);
        hi[i] = h;
        lo[i] = __float2bfloat16(x - __bfloat162float(h));
    }
}

// ---------------- embedding ---------------------------------------------------
__global__ void embed_kernel(const float* __restrict__ in,
                             const float* __restrict__ W,
                             const float* __restrict__ b,
                             __nv_bfloat16* __restrict__ yhi,
                             __nv_bfloat16* __restrict__ ylo) {
    int ln = blockIdx.x;
    int e  = blockIdx.y * 256 + threadIdx.x;
    __shared__ float xs[KIN];
    if (threadIdx.x < KIN) xs[threadIdx.x] = in[(size_t)ln * KIN + threadIdx.x];
    __syncthreads();
    float acc = b[e];
    const float* w = W + (size_t)e * KIN;
#pragma unroll
    for (int k = 0; k < KIN; k++) acc = fmaf(xs[k], w[k], acc);
    __nv_bfloat16 hh, hl;
    split2(acc, hh, hl);
    yhi[(size_t)ln * EDIM + e] = hh;
    ylo[(size_t)ln * EDIM + e] = hl;
}

// ---------------- bf16-split MMA GEMM (input projections) --------------------
__global__ void __launch_bounds__(256)
gemm_xg_mma(const __nv_bfloat16* __restrict__ Ahi,
            const __nv_bfloat16* __restrict__ Alo,
            const __nv_bfloat16* __restrict__ Bhi,
            const __nv_bfloat16* __restrict__ Blo,
            const float* __restrict__ bias,
            float* __restrict__ C) {
    __shared__ __nv_bfloat16 sA[2][128][40];
    __shared__ __nv_bfloat16 sB[2][64][40];
    const int tid = threadIdx.x, lane = tid & 31, warp = tid >> 5;
    const int wm = warp >> 1, wn = warp & 1;
    const int bm = blockIdx.y * 128, bn = blockIdx.x * 64;

    float c[2][4][4];
#pragma unroll
    for (int m = 0; m < 2; m++)
#pragma unroll
        for (int n = 0; n < 4; n++)
#pragma unroll
            for (int q = 0; q < 4; q++) c[m][n][q] = 0.f;

    for (int k0 = 0; k0 < EDIM; k0 += 32) {
        __syncthreads();
        for (int i = tid; i < 512; i += 256) {
            int r = i >> 2, cv = i & 3;
            *(uint4*)&sA[0][r][cv * 8] = *(const uint4*)(Ahi + (size_t)(bm + r) * EDIM + k0 + cv * 8);
            *(uint4*)&sA[1][r][cv * 8] = *(const uint4*)(Alo + (size_t)(bm + r) * EDIM + k0 + cv * 8);
        }
        if (tid < 256) {
            int r = tid >> 2, cv = tid & 3;
            *(uint4*)&sB[0][r][cv * 8] = *(const uint4*)(Bhi + (size_t)(bn + r) * EDIM + k0 + cv * 8);
            *(uint4*)&sB[1][r][cv * 8] = *(const uint4*)(Blo + (size_t)(bn + r) * EDIM + k0 + cv * 8);
        }
        __syncthreads();

        uint32_t a[2][2][2][4];
#pragma unroll
        for (int s = 0; s < 2; s++)
#pragma unroll
            for (int m = 0; m < 2; m++) {
                int arow = wm * 32 + m * 16 + (lane & 15);
                int acol = (lane >> 4) * 8;
                uint32_t ad = smem_u32(&sA[s][arow][acol]);
                ldsm_x4(a[s][m][0], ad);
                ldsm_x4(a[s][m][1], ad + 32);
            }
        uint32_t bf[2][4][4];
#pragma unroll
        for (int s = 0; s < 2; s++)
#pragma unroll
            for (int n = 0; n < 4; n++) {
                int brow = wn * 32 + n * 8 + (lane & 7);
                int bcol = (lane >> 3) * 8;
                ldsm_x4(bf[s][n], smem_u32(&sB[s][brow][bcol]));
            }
#pragma unroll
        for (int m = 0; m < 2; m++)
#pragma unroll
            for (int n = 0; n < 4; n++)
#pragma unroll
                for (int k = 0; k < 2; k++) {
                    mma16816(c[m][n], a[0][m][k], bf[0][n][k * 2], bf[0][n][k * 2 + 1]);
                    mma16816(c[m][n], a[0][m][k], bf[1][n][k * 2], bf[1][n][k * 2 + 1]);
                    mma16816(c[m][n], a[1][m][k], bf[0][n][k * 2], bf[0][n][k * 2 + 1]);
                }
    }

#pragma unroll
    for (int m = 0; m < 2; m++) {
        int row0 = bm + wm * 32 + m * 16 + (lane >> 2);
#pragma unroll
        for (int n = 0; n < 4; n++) {
            int col = bn + wn * 32 + n * 8 + (lane & 3) * 2;
            float2 bb = *(const float2*)(bias + col);
            float2 v0 = make_float2(c[m][n][0] + bb.x, c[m][n][1] + bb.y);
            float2 v1 = make_float2(c[m][n][2] + bb.x, c[m][n][3] + bb.y);
            *(float2*)(C + (size_t)row0 * H3 + col) = v0;
            *(float2*)(C + (size_t)(row0 + 8) * H3 + col) = v1;
        }
    }
}

// ---------------- persistent GRU layer: bulk-DMA staged h ---------------------
// 256 threads (8 warps: 4 wm x 2 wk). Block owns 8 hidden cols (24 W rows,
// resident in smem). h broadcast: 8 chunks x 32KB per step, each ONE
// cp.async.bulk into a double buffer, completion via mbarrier.
__global__ void __launch_bounds__(256, 1)
gru_layer_mma(const float* __restrict__ xg,
              const __nv_bfloat16* __restrict__ whh_hi,
              const __nv_bfloat16* __restrict__ whh_lo,
              const float* __restrict__ bhh,
              __nv_bfloat16* __restrict__ h2,
              __nv_bfloat16* __restrict__ yhi,
              __nv_bfloat16* __restrict__ ylo) {
    extern __shared__ __align__(16) char smem[];
    __nv_bfloat16* ws_hi  = (__nv_bfloat16*)(smem + WS_HI_OFF);
    __nv_bfloat16* ws_lo  = (__nv_bfloat16*)(smem + WS_LO_OFF);
    float*         red    = (float*)(smem + RED_OFF);
    __nv_bfloat16* sm_out = (__nv_bfloat16*)(smem + SMOUT_OFF);
    const uint32_t smem_base = smem_u32(smem);
    const uint32_t hb_base = smem_base + HB_OFF;
    const uint32_t mb0 = smem_base + MB0_OFF;
    const uint32_t mb1 = smem_base + MB1_OFF;

    const int tid  = threadIdx.x;
    const int lane = tid & 31, warp = tid >> 5;
    const int wm = warp & 3, wk = warp >> 2;
    const int bid = blockIdx.x;
    const int j0 = bid * 8;
    const int g0 = (j0 >> 3) & 15;      // 16B group of this block's cols
    const int chn0 = j0 >> 7;           // chunk of this block's cols

    if (tid == 0) {
        MBARRIER_INIT(mb0, 1);
        MBARRIER_INIT(mb1, 1);
    }

    // W tile -> smem (rows r = g*8+jj -> global row g*HDIM + j0 + jj)
    for (int i = tid; i < 24 * 128; i += 256) {
        int r = i >> 7, v = i & 127;
        int grow = (r >> 3) * HDIM + j0 + (r & 7);
        *(uint4*)&ws_hi[r * WS_LD + v * 8] = *(const uint4*)(whh_hi + (size_t)grow * HDIM + v * 8);
        *(uint4*)&ws_lo[r * WS_LD + v * 8] = *(const uint4*)(whh_lo + (size_t)grow * HDIM + v * 8);
    }
    // zero h slot 0: block zeros its 1024-element slice
    *(uint2*)&h2[bid * 1024 + tid * 4] = make_uint2(0u, 0u);
    __syncthreads();

    unsigned bar_t = ((volatile unsigned*)g_flags)[bid];
    flag_barrier(bid, ++bar_t);

    int wc0 = 0, wc1 = 0;

    for (int t = 0; t < LSEQ; t++) {
        const __nv_bfloat16* hsrc = h2 + (size_t)(t & 1) * H2_SLOT;
        __nv_bfloat16* hdst = h2 + (size_t)((t + 1) & 1) * H2_SLOT;
        const float* xg_t = xg + (size_t)t * NB * H3;

        // kick off chunk 0 bulk copy
        if (tid == 0) {
            MBARRIER_EXPECT_TX(mb0, 32768);
            bulk_copy(hb_base, hsrc, 32768, mb0);
        }

        // prefetch epilogue operands (wk==0 warps do gates)
        float xr_[4], xz_[4], xn_[4], hp_[4];
        if (wk == 0) {
#pragma unroll
            for (int q = 0; q < 4; q++) {
                int b  = wm * 16 + (lane >> 2) + (q >> 1) * 8;
                int ja = j0 + (lane & 3) * 2 + (q & 1);
                const float* xr = xg_t + (size_t)b * H3 + ja;
                xr_[q] = xr[0];
                xz_[q] = xr[HDIM];
                xn_[q] = xr[2 * HDIM];
                int e = chn0 * 16384 + b * 128 + ((g0 ^ (b & 7)) << 3) + (ja & 7);
                hp_[q] = __bfloat162float(hsrc[e]) + __bfloat162float(hsrc[e + 8192]);
            }
        }

        float c[3][4];
#pragma unroll
        for (int i = 0; i < 3; i++)
#pragma unroll
            for (int q = 0; q < 4; q++) c[i][q] = 0.f;

        for (int ch = 0; ch < 8; ch++) {
            const int buf = ch & 1;
            // issue next chunk into the other buffer (free since chunk ch-1)
            if (ch < 7 && tid == 0) {
                uint32_t mbn = (buf == 0) ? mb1 : mb0;
                MBARRIER_EXPECT_TX(mbn, 32768);
                bulk_copy(hb_base + (1 - buf) * 32768,
                          hsrc + (size_t)(ch + 1) * 16384, 32768, mbn);
            }
            if (buf == 0) { MBARRIER_WAIT_PARITY(mb0, wc0 & 1); wc0++; }
            else          { MBARRIER_WAIT_PARITY(mb1, wc1 & 1); wc1++; }

            const uint32_t bufb = hb_base + buf * 32768;
            const int arow = wm * 16 + (lane & 15);
            const int rx = arow & 7;
            const uint32_t rowb = bufb + arow * 256;
#pragma unroll
            for (int k32 = 0; k32 < 2; k32++) {
                const int gb = wk * 8 + k32 * 4 + (lane >> 4);
                uint32_t a0 = rowb + (uint32_t)((gb ^ rx) << 4);
                uint32_t a1 = rowb + (uint32_t)(((gb + 2) ^ rx) << 4);
                uint32_t a_hi[2][4], a_lo[2][4];
                ldsm_x4(a_hi[0], a0);          ldsm_x4(a_hi[1], a1);
                ldsm_x4(a_lo[0], a0 + 16384);  ldsm_x4(a_lo[1], a1 + 16384);

                uint32_t b_hi[3][4], b_lo[3][4];
                int bkcol = ch * 128 + wk * 64 + k32 * 32 + (lane >> 3) * 8;
#pragma unroll
                for (int n8 = 0; n8 < 3; n8++) {
                    int brow = n8 * 8 + (lane & 7);
                    ldsm_x4(b_hi[n8], smem_u32(&ws_hi[brow * WS_LD + bkcol]));
                    ldsm_x4(b_lo[n8], smem_u32(&ws_lo[brow * WS_LD + bkcol]));
                }
#pragma unroll
                for (int n8 = 0; n8 < 3; n8++)
#pragma unroll
                    for (int k = 0; k < 2; k++) {
                        mma16816(c[n8], a_hi[k], b_hi[n8][k * 2], b_hi[n8][k * 2 + 1]);
                        mma16816(c[n8], a_hi[k], b_lo[n8][k * 2], b_lo[n8][k * 2 + 1]);
                        mma16816(c[n8], a_lo[k], b_hi[n8][k * 2], b_hi[n8][k * 2 + 1]);
                    }
            }
            __syncthreads();   // all warps done reading buf -> refillable
        }

        // combine k-halves
        if (wk == 1) {
            float* rp = red + ((size_t)wm * 32 + lane) * 12;
#pragma unroll
            for (int i = 0; i < 3; i++)
#pragma unroll
                for (int q = 0; q < 4; q++) rp[i * 4 + q] = c[i][q];
        }
        __syncthreads();
        if (wk == 0) {
            const float* rp = red + ((size_t)wm * 32 + lane) * 12;
#pragma unroll
            for (int q = 0; q < 4; q++) {
                int jj = (lane & 3) * 2 + (q & 1);
                int ja = j0 + jj;
                int b  = wm * 16 + (lane >> 2) + (q >> 1) * 8;
                float hr = c[0][q] + rp[0 * 4 + q] + bhh[ja];
                float hz = c[1][q] + rp[1 * 4 + q] + bhh[HDIM + ja];
                float hn = c[2][q] + rp[2 * 4 + q] + bhh[2 * HDIM + ja];
                float r = sigmoidf_(xr_[q] + hr);
                float z = sigmoidf_(xz_[q] + hz);
                float n = tanhf(xn_[q] + r * hn);
                float hnew = (1.f - z) * n + z * hp_[q];
                __nv_bfloat16 hh, hl;
                split2(hnew, hh, hl);
                sm_out[b * 8 + jj] = hh;
                sm_out[512 + b * 8 + jj] = hl;
            }
        }
        __syncthreads();

        // h_out store (swizzled chunk layout), barrier, then y
        uint4 v;
        int b_ = tid & 63, s_ = tid >> 6;
        if (tid < 128) {
            v = *(const uint4*)&sm_out[s_ * 512 + b_ * 8];
            int e = chn0 * 16384 + s_ * 8192 + b_ * 128 + ((g0 ^ (b_ & 7)) << 3);
            *(uint4*)&hdst[e] = v;
        }

        flag_barrier(bid, ++bar_t);

        if (tid < 128) {
            __nv_bfloat16* ydst = (s_ == 0 ? yhi : ylo);
            *(uint4*)&ydst[(size_t)t * NB * HDIM + b_ * HDIM + j0] = v;
        }
    }
}

// ---------------- output projection ------------------------------------------
__global__ void outproj_kernel(const __nv_bfloat16* __restrict__ xhi,
                               const __nv_bfloat16* __restrict__ xlo,
                               const float* __restrict__ W,
                               const float* __restrict__ b,
                               float* __restrict__ out) {
    int ln = blockIdx.x;
    __shared__ float xs[HDIM];
    const __nv_bfloat16* xh = xhi + (size_t)ln * HDIM;
    const __nv_bfloat16* xl = xlo + (size_t)ln * HDIM;
    for (int k = threadIdx.x; k < HDIM; k += 256)
        xs[k] = __bfloat162float(xh[k]) + __bfloat162float(xl[k]);
    __syncthreads();
    int warp = threadIdx.x >> 5, lane = threadIdx.x & 31;
    for (int c = warp; c < NC; c += 8) {
        const float* w = W + (size_t)c * HDIM;
        float acc = 0.f;
        for (int k = lane; k < HDIM; k += 32) acc = fmaf(xs[k], w[k], acc);
#pragma unroll
        for (int o = 16; o; o >>= 1) acc += __shfl_xor_sync(0xffffffffu, acc, o);
        if (lane == 0) out[(size_t)ln * NC + c] = acc + b[c];
    }
}

// ---------------- orchestration ---------------------------------------------
extern "C" void kernel_launch(void* const* d_in, const int* in_sizes, int n_in,
                              void* d_out, int out_size) {
    const float* inputs = (const float*)d_in[0];
    const float* emb_W  = (const float*)d_in[1];
    const float* emb_b  = (const float*)d_in[2];
    const float* w_ih   = (const float*)d_in[3];
    const float* w_hh   = (const float*)d_in[4];
    const float* b_ih   = (const float*)d_in[5];
    const float* b_hh   = (const float*)d_in[6];
    const float* out_W  = (const float*)d_in[7];
    const float* out_b  = (const float*)d_in[8];
    float* out = (float*)d_out;

    float *xg;
    __nv_bfloat16 *yhi, *ylo, *h2, *wih_hi, *wih_lo, *whh_hi, *whh_lo;
    cudaGetSymbolAddress((void**)&xg,     g_xg);
    cudaGetSymbolAddress((void**)&yhi,    g_y_hi);
    cudaGetSymbolAddress((void**)&ylo,    g_y_lo);
    cudaGetSymbolAddress((void**)&h2,     g_h2);
    cudaGetSymbolAddress((void**)&wih_hi, g_wih_hi);
    cudaGetSymbolAddress((void**)&wih_lo, g_wih_lo);
    cudaGetSymbolAddress((void**)&whh_hi, g_whh_hi);
    cudaGetSymbolAddress((void**)&whh_lo, g_whh_lo);

    cudaFuncSetAttribute(gru_layer_mma,
                         cudaFuncAttributeMaxDynamicSharedMemorySize, GRU_SMEM);

    const int M = LSEQ * NB;

    split_kernel<<<4096, 256>>>(w_ih, wih_hi, wih_lo, NL * H3 * EDIM);
    split_kernel<<<4096, 256>>>(w_hh, whh_hi, whh_lo, NL * H3 * HDIM);

    {
        dim3 grid(M, EDIM / 256);
        embed_kernel<<<grid, 256>>>(inputs, emb_W, emb_b, yhi, ylo);
    }

    for (int l = 0; l < NL; l++) {
        {
            dim3 grid(H3 / 64, M / 128);
            gemm_xg_mma<<<grid, 256>>>(yhi, ylo,
                                       wih_hi + (size_t)l * H3 * EDIM,
                                       wih_lo + (size_t)l * H3 * EDIM,
                                       b_ih + (size_t)l * H3,
                                       xg);
        }
        gru_layer_mma<<<GRU_BLOCKS, 256, GRU_SMEM>>>(
            xg,
            whh_hi + (size_t)l * H3 * HDIM,
            whh_lo + (size_t)l * H3 * HDIM,
            b_hh + (size_t)l * H3,
            h2, yhi, ylo);
    }

    outproj_kernel<<<M, 256>>>(yhi, ylo, out_W, out_b, out);

    (void)in_sizes; (void)n_in; (void)out_size;
}